// round 2
// baseline (speedup 1.0000x reference)
#include <cuda_runtime.h>
#include <math.h>

#define Bsz 2
#define Npts 4096
#define Mpts 4096
#define KK 32
#define CC 64
#define R2 0.0064f

// ---------------- device scratch (no allocs allowed) ----------------
__device__ float g_featT[Bsz * Mpts * CC];   // feat transposed to [b][m][c]
__device__ int   g_idx[Bsz * Npts * KK];     // ball query indices (compacted)
__device__ int   g_cnt[Bsz * Npts];          // neighbor counts
__device__ float g_rowpart[128];             // per-block partial sums: min over m
__device__ float g_colpart[128];             // per-block partial sums: min over n
__device__ unsigned int g_counter;           // work queue for mlp kernel

// ---------------- prep: transpose feat + reset counter ----------------
__global__ void prep_kernel(const float* __restrict__ feat) {
    __shared__ float tile[32][33];
    int b  = blockIdx.z;
    int m0 = blockIdx.x * 32;
    int c0 = blockIdx.y * 32;
    int tx = threadIdx.x, ty = threadIdx.y; // block (32, 8)
    if (blockIdx.x == 0 && blockIdx.y == 0 && blockIdx.z == 0 && tx == 0 && ty == 0)
        g_counter = 0u;
#pragma unroll
    for (int r = 0; r < 32; r += 8)
        tile[ty + r][tx] = feat[(b * CC + (c0 + ty + r)) * Mpts + m0 + tx];
    __syncthreads();
#pragma unroll
    for (int r = 0; r < 32; r += 8)
        g_featT[((size_t)(b * Mpts + (m0 + ty + r))) * CC + c0 + tx] = tile[tx][ty + r];
}

// ---------------- distance scan: ball query + both min reductions ----------------
// blocks [0,128): row task  (per n: scan m -> ball query + min over m)
// blocks [128,256): col task (per m: scan n -> min over n)
__global__ void dist_kernel(const float* __restrict__ points,
                            const float* __restrict__ knnpoints) {
    extern __shared__ __align__(16) unsigned char smem_raw[];
    float4* sh  = (float4*)smem_raw;          // 4096 entries (x,y,z,|q|^2)
    float*  red = (float*)(sh + Mpts);        // 64-float reduction buffer

    bool row = blockIdx.x < 128;
    int  ib  = row ? blockIdx.x : blockIdx.x - 128;
    int  i   = ib * 64 + threadIdx.x;         // 0..8191
    int  b   = i >> 12;

    const float* scan = row ? knnpoints : points;
    for (int m = threadIdx.x; m < 4096; m += 64) {
        float qx = scan[(b * 3 + 0) * 4096 + m];
        float qy = scan[(b * 3 + 1) * 4096 + m];
        float qz = scan[(b * 3 + 2) * 4096 + m];
        sh[m] = make_float4(qx, qy, qz, fmaf(qx, qx, fmaf(qy, qy, qz * qz)));
    }
    __syncthreads();

    int x = i & 4095;
    const float* own = row ? points : knnpoints;
    float px = own[(b * 3 + 0) * 4096 + x];
    float py = own[(b * 3 + 1) * 4096 + x];
    float pz = own[(b * 3 + 2) * 4096 + x];
    float pe = fmaf(px, px, fmaf(py, py, pz * pz));

    float minv = 3.402823e38f;
    int   cnt  = 0;
    int   base = i * KK;

    for (int m0 = 0; m0 < 4096; m0 += 4) {
        float d2v[4];
#pragma unroll
        for (int u = 0; u < 4; u++) {
            float4 q = sh[m0 + u];
            float dot = fmaf(px, q.x, fmaf(py, q.y, pz * q.z));
            d2v[u] = fmaxf(pe + q.w - 2.0f * dot, 0.0f);
        }
        minv = fminf(minv, fminf(fminf(d2v[0], d2v[1]), fminf(d2v[2], d2v[3])));
        if (row) {
            bool p0 = d2v[0] < R2, p1 = d2v[1] < R2, p2 = d2v[2] < R2, p3 = d2v[3] < R2;
            if (p0 | p1 | p2 | p3) {            // rare path
                if (p0 && cnt < KK) { g_idx[base + cnt] = m0 + 0; cnt++; }
                if (p1 && cnt < KK) { g_idx[base + cnt] = m0 + 1; cnt++; }
                if (p2 && cnt < KK) { g_idx[base + cnt] = m0 + 2; cnt++; }
                if (p3 && cnt < KK) { g_idx[base + cnt] = m0 + 3; cnt++; }
            }
        }
    }
    if (row) {
        if (cnt == 0) g_idx[base] = 0;   // reference fill semantics: idx -> 0 when no hit
        g_cnt[i] = cnt;
    }
    float cd = sqrtf(1e-6f + minv);
    red[threadIdx.x] = cd;
    __syncthreads();
    for (int s = 32; s > 0; s >>= 1) {
        if (threadIdx.x < s) red[threadIdx.x] += red[threadIdx.x + s];
        __syncthreads();
    }
    if (threadIdx.x == 0) {
        if (row) g_rowpart[ib] = red[0];
        else     g_colpart[ib] = red[0];
    }
}

// ---------------- fused gather + MLP + aggregate ----------------
#define NWARP 16
#define OFF_W1 0
#define OFF_W2 8704
#define OFF_W3 16896
#define OFF_B1 20992
#define OFF_B2 21120
#define OFF_B3 21184
#define OFF_WARP 21248
#define WARP_STRIDE 2080
#define OFF_XS 0
#define OFF_H1 544
#define OFF_H2 1568
#define SMEM_FLOATS (OFF_WARP + NWARP * WARP_STRIDE)

__global__ void __launch_bounds__(512, 1) mlp_kernel(
    const float* __restrict__ points, const float* __restrict__ knnpoints,
    const float* __restrict__ w1, const float* __restrict__ b1,
    const float* __restrict__ w2, const float* __restrict__ b2,
    const float* __restrict__ w3, const float* __restrict__ b3,
    float* __restrict__ out)
{
    extern __shared__ __align__(16) unsigned char smem_raw2[];
    float* sm = (float*)smem_raw2;
    int tid = threadIdx.x;

    // weights transposed: w?t[c][o]  (stride-1 in o -> coalesced vector loads)
    for (int e = tid; e < 128 * 68; e += 512) {
        int o = e / 68, c = e % 68;
        sm[OFF_W1 + c * 128 + o] = w1[e];
    }
    for (int e = tid; e < 64 * 128; e += 512) {
        int o = e >> 7, c = e & 127;
        sm[OFF_W2 + c * 64 + o] = w2[e];
    }
    for (int e = tid; e < 64 * 64; e += 512) {
        int o = e >> 6, c = e & 63;
        sm[OFF_W3 + c * 64 + o] = w3[e];
    }
    if (tid < 128) sm[OFF_B1 + tid] = b1[tid];
    if (tid < 64)  sm[OFF_B2 + tid] = b2[tid];
    if (tid < 64)  sm[OFF_B3 + tid] = b3[tid];
    __syncthreads();

    int lane = tid & 31;
    int wrp  = tid >> 5;
    float*  ws  = sm + OFF_WARP + wrp * WARP_STRIDE;
    float4* xv  = (float4*)(ws + OFF_XS);   // 8 cols x 17 float4 (64 feat + diff + dist)
    float4* h1v = (float4*)(ws + OFF_H1);   // 8 cols x 32 float4
    float4* h2v = (float4*)(ws + OFF_H2);   // 8 cols x 16 float4
    float2* h2s = (float2*)(ws + OFF_H2);
    const float4* w1v = (const float4*)(sm + OFF_W1);
    const float2* w2v = (const float2*)(sm + OFF_W2);
    const float2* w3v = (const float2*)(sm + OFF_W3);

    for (;;) {
        int i = 0;
        if (lane == 0) i = (int)atomicAdd(&g_counter, 1u);
        i = __shfl_sync(0xffffffffu, i, 0);
        if (i >= Bsz * Npts) break;
        int b = i >> 12, n = i & 4095;

        float px = points[(b * 3 + 0) * 4096 + n];
        float py = points[(b * 3 + 1) * 4096 + n];
        float pz = points[(b * 3 + 2) * 4096 + n];

        int   cnt     = g_cnt[i];
        int   cols    = cnt > 0 ? cnt : 1;
        float w0extra = (float)(KK - cols + 1);   // fill column weight (exact dedup)
        int   ngroups = (cols + 7) >> 3;
        int   base    = i * KK;
        float agg0 = 0.f, agg1 = 0.f;

        for (int g = 0; g < ngroups; g++) {
            int jbase = g * 8;
            // ---- build x (8 columns) ----
            {
                int half = lane >> 4, l16 = lane & 15;
#pragma unroll
                for (int jp = 0; jp < 4; jp++) {
                    int j  = jp * 2 + half;
                    int jj = jbase + j; if (jj >= cols) jj = cols - 1;
                    int m  = g_idx[base + jj];
                    const float4* fs = (const float4*)(g_featT + ((size_t)(b * 4096 + m)) * 64);
                    xv[j * 17 + l16] = fs[l16];
                }
                if (lane < 8) {
                    int j  = lane;
                    int jj = jbase + j; if (jj >= cols) jj = cols - 1;
                    int m  = g_idx[base + jj];
                    float qx = knnpoints[(b * 3 + 0) * 4096 + m];
                    float qy = knnpoints[(b * 3 + 1) * 4096 + m];
                    float qz = knnpoints[(b * 3 + 2) * 4096 + m];
                    float dx = qx - px, dy = qy - py, dz = qz - pz;
                    float dd = fmaf(dx, dx, fmaf(dy, dy, dz * dz));
                    xv[j * 17 + 16] = make_float4(dx, dy, dz, dd);
                }
            }
            __syncwarp();
            // ---- layer 1: 68 -> 128 (lane owns o = 4*lane..4*lane+3) ----
            {
                float a0[8], a1[8], a2[8], a3[8];
                float bb0 = sm[OFF_B1 + 4 * lane + 0];
                float bb1 = sm[OFF_B1 + 4 * lane + 1];
                float bb2 = sm[OFF_B1 + 4 * lane + 2];
                float bb3 = sm[OFF_B1 + 4 * lane + 3];
#pragma unroll
                for (int j = 0; j < 8; j++) { a0[j] = bb0; a1[j] = bb1; a2[j] = bb2; a3[j] = bb3; }
#pragma unroll
                for (int c4 = 0; c4 < 17; c4++) {
                    float4 wA = w1v[(4 * c4 + 0) * 32 + lane];
                    float4 wB = w1v[(4 * c4 + 1) * 32 + lane];
                    float4 wC = w1v[(4 * c4 + 2) * 32 + lane];
                    float4 wD = w1v[(4 * c4 + 3) * 32 + lane];
#pragma unroll
                    for (int j = 0; j < 8; j++) {
                        float4 x4 = xv[j * 17 + c4];
                        a0[j] = fmaf(wA.x, x4.x, a0[j]); a1[j] = fmaf(wA.y, x4.x, a1[j]);
                        a2[j] = fmaf(wA.z, x4.x, a2[j]); a3[j] = fmaf(wA.w, x4.x, a3[j]);
                        a0[j] = fmaf(wB.x, x4.y, a0[j]); a1[j] = fmaf(wB.y, x4.y, a1[j]);
                        a2[j] = fmaf(wB.z, x4.y, a2[j]); a3[j] = fmaf(wB.w, x4.y, a3[j]);
                        a0[j] = fmaf(wC.x, x4.z, a0[j]); a1[j] = fmaf(wC.y, x4.z, a1[j]);
                        a2[j] = fmaf(wC.z, x4.z, a2[j]); a3[j] = fmaf(wC.w, x4.z, a3[j]);
                        a0[j] = fmaf(wD.x, x4.w, a0[j]); a1[j] = fmaf(wD.y, x4.w, a1[j]);
                        a2[j] = fmaf(wD.z, x4.w, a2[j]); a3[j] = fmaf(wD.w, x4.w, a3[j]);
                    }
                }
#pragma unroll
                for (int j = 0; j < 8; j++)
                    h1v[j * 32 + lane] = make_float4(fmaxf(a0[j], 0.f), fmaxf(a1[j], 0.f),
                                                     fmaxf(a2[j], 0.f), fmaxf(a3[j], 0.f));
            }
            __syncwarp();
            // ---- layer 2: 128 -> 64 (lane owns o = 2*lane, 2*lane+1) ----
            {
                float c0a[8], c1a[8];
                float bb0 = sm[OFF_B2 + 2 * lane + 0];
                float bb1 = sm[OFF_B2 + 2 * lane + 1];
#pragma unroll
                for (int j = 0; j < 8; j++) { c0a[j] = bb0; c1a[j] = bb1; }
#pragma unroll
                for (int c4 = 0; c4 < 32; c4++) {
                    float2 wA = w2v[(4 * c4 + 0) * 32 + lane];
                    float2 wB = w2v[(4 * c4 + 1) * 32 + lane];
                    float2 wC = w2v[(4 * c4 + 2) * 32 + lane];
                    float2 wD = w2v[(4 * c4 + 3) * 32 + lane];
#pragma unroll
                    for (int j = 0; j < 8; j++) {
                        float4 x4 = h1v[j * 32 + c4];
                        c0a[j] = fmaf(wA.x, x4.x, c0a[j]); c1a[j] = fmaf(wA.y, x4.x, c1a[j]);
                        c0a[j] = fmaf(wB.x, x4.y, c0a[j]); c1a[j] = fmaf(wB.y, x4.y, c1a[j]);
                        c0a[j] = fmaf(wC.x, x4.z, c0a[j]); c1a[j] = fmaf(wC.y, x4.z, c1a[j]);
                        c0a[j] = fmaf(wD.x, x4.w, c0a[j]); c1a[j] = fmaf(wD.y, x4.w, c1a[j]);
                    }
                }
#pragma unroll
                for (int j = 0; j < 8; j++)
                    h2s[j * 32 + lane] = make_float2(fmaxf(c0a[j], 0.f), fmaxf(c1a[j], 0.f));
            }
            __syncwarp();
            // ---- layer 3: 64 -> 64 + aggregate ----
            {
                float d0a[8], d1a[8];
                float bb0 = sm[OFF_B3 + 2 * lane + 0];
                float bb1 = sm[OFF_B3 + 2 * lane + 1];
#pragma unroll
                for (int j = 0; j < 8; j++) { d0a[j] = bb0; d1a[j] = bb1; }
#pragma unroll
                for (int c4 = 0; c4 < 16; c4++) {
                    float2 wA = w3v[(4 * c4 + 0) * 32 + lane];
                    float2 wB = w3v[(4 * c4 + 1) * 32 + lane];
                    float2 wC = w3v[(4 * c4 + 2) * 32 + lane];
                    float2 wD = w3v[(4 * c4 + 3) * 32 + lane];
#pragma unroll
                    for (int j = 0; j < 8; j++) {
                        float4 x4 = h2v[j * 16 + c4];
                        d0a[j] = fmaf(wA.x, x4.x, d0a[j]); d1a[j] = fmaf(wA.y, x4.x, d1a[j]);
                        d0a[j] = fmaf(wB.x, x4.y, d0a[j]); d1a[j] = fmaf(wB.y, x4.y, d1a[j]);
                        d0a[j] = fmaf(wC.x, x4.z, d0a[j]); d1a[j] = fmaf(wC.y, x4.z, d1a[j]);
                        d0a[j] = fmaf(wD.x, x4.w, d0a[j]); d1a[j] = fmaf(wD.y, x4.w, d1a[j]);
                    }
                }
#pragma unroll
                for (int j = 0; j < 8; j++) {
                    int jj = jbase + j;
                    float wj = (jj == 0) ? w0extra : ((jj < cols) ? 1.0f : 0.0f);
                    agg0 = fmaf(wj, fmaxf(d0a[j], 0.f), agg0);
                    agg1 = fmaf(wj, fmaxf(d1a[j], 0.f), agg1);
                }
            }
            __syncwarp();
        }
        out[((size_t)(b * 64 + 2 * lane + 0)) * 4096 + n] = agg0;
        out[((size_t)(b * 64 + 2 * lane + 1)) * 4096 + n] = agg1;
    }
}

// ---------------- deterministic final loss reduction ----------------
__global__ void loss_kernel(float* __restrict__ out, int pos) {
    int lane = threadIdx.x;
    float s = 0.f;
    for (int t = lane; t < 128; t += 32) s += g_rowpart[t] + g_colpart[t];
#pragma unroll
    for (int off = 16; off > 0; off >>= 1) s += __shfl_xor_sync(0xffffffffu, s, off);
    if (lane == 0) out[pos] = s * (1.0f / 8192.0f);
}

extern "C" void kernel_launch(void* const* d_in, const int* in_sizes, int n_in,
                              void* d_out, int out_size) {
    const float* points    = (const float*)d_in[0];
    const float* knnpoints = (const float*)d_in[1];
    const float* feat      = (const float*)d_in[2];
    const float* w1 = (const float*)d_in[3];
    const float* b1 = (const float*)d_in[4];
    const float* w2 = (const float*)d_in[5];
    const float* b2 = (const float*)d_in[6];
    const float* w3 = (const float*)d_in[7];
    const float* b3 = (const float*)d_in[8];
    float* out = (float*)d_out;

    cudaFuncSetAttribute(dist_kernel, cudaFuncAttributeMaxDynamicSharedMemorySize, 65792);
    cudaFuncSetAttribute(mlp_kernel,  cudaFuncAttributeMaxDynamicSharedMemorySize, SMEM_FLOATS * 4);

    int nsm = 148;
    cudaDeviceGetAttribute(&nsm, cudaDevAttrMultiProcessorCount, 0);

    dim3 tb(32, 8);
    dim3 tg(Mpts / 32, CC / 32, Bsz);
    prep_kernel<<<tg, tb>>>(feat);
    dist_kernel<<<256, 64, 65792>>>(points, knnpoints);
    mlp_kernel<<<nsm, 512, SMEM_FLOATS * 4>>>(points, knnpoints, w1, b1, w2, b2, w3, b3, out);
    loss_kernel<<<1, 32>>>(out, Bsz * 64 * Npts);
}

// round 7
// speedup vs baseline: 1.5374x; 1.5374x over previous
#include <cuda_runtime.h>
#include <math.h>

#define Bsz 2
#define Npts 4096
#define Mpts 4096
#define KK 32
#define CC 64
#define R2 0.0064f

// ---------------- device scratch (no allocs allowed) ----------------
__device__ float g_featT[Bsz * Mpts * CC];   // feat transposed to [b][m][c]
__device__ int   g_idx[Bsz * Npts * KK];     // ball query indices (compacted)
__device__ int   g_cnt[Bsz * Npts];          // neighbor counts
__device__ float g_rowpart[128];             // per-block partial sums: min over m
__device__ float g_colpart[128];             // per-block partial sums: min over n
__device__ unsigned int g_counter;           // work queue for mlp kernel

// ---------------- packed f32x2 helpers ----------------
__device__ __forceinline__ unsigned long long packdup(float a) {
    unsigned long long r;
    asm("mov.b64 %0, {%1, %1};" : "=l"(r) : "f"(a));
    return r;
}
__device__ __forceinline__ void unpack2(unsigned long long v, float& a, float& b) {
    asm("mov.b64 {%0, %1}, %2;" : "=f"(a), "=f"(b) : "l"(v));
}
__device__ __forceinline__ void fma2(unsigned long long& d, unsigned long long a,
                                     unsigned long long b) {
    asm("fma.rn.f32x2 %0, %1, %2, %0;" : "+l"(d) : "l"(a), "l"(b));
}

// ---------------- prep: transpose feat + reset counter ----------------
__global__ void prep_kernel(const float* __restrict__ feat) {
    __shared__ float tile[32][33];
    int b  = blockIdx.z;
    int m0 = blockIdx.x * 32;
    int c0 = blockIdx.y * 32;
    int tx = threadIdx.x, ty = threadIdx.y; // block (32, 8)
    if (blockIdx.x == 0 && blockIdx.y == 0 && blockIdx.z == 0 && tx == 0 && ty == 0)
        g_counter = 0u;
#pragma unroll
    for (int r = 0; r < 32; r += 8)
        tile[ty + r][tx] = feat[(b * CC + (c0 + ty + r)) * Mpts + m0 + tx];
    __syncthreads();
#pragma unroll
    for (int r = 0; r < 32; r += 8)
        g_featT[((size_t)(b * Mpts + (m0 + ty + r))) * CC + c0 + tx] = tile[tx][ty + r];
}

// ---------------- distance scan: 4 threads per point ----------------
// blocks [0,128): row task (per n: ball query + min over m)
// blocks [128,256): col task (per m: min over n)
// block = 256 threads = 64 points x 4 quarter-scans
#define DIST_SMEM (4100 * 16 + 64 * 4 * 32 * 4 + 64 * 4)
__global__ void dist_kernel(const float* __restrict__ points,
                            const float* __restrict__ knnpoints) {
    extern __shared__ __align__(16) unsigned char smem_raw[];
    float4* sh  = (float4*)smem_raw;                 // 4100 entries (quarter-staggered)
    int*    buf = (int*)(sh + 4100);                 // [64][4][32] hit scratch
    float*  red = (float*)(buf + 64 * 4 * 32);       // 64-float reduction buffer

    int t  = threadIdx.x;
    bool row = blockIdx.x < 128;
    int  ib  = row ? blockIdx.x : blockIdx.x - 128;
    int  pp  = t >> 2;                // point slot in block (0..63)
    int  q   = t & 3;                 // quarter
    int  i   = ib * 64 + pp;          // 0..8191
    int  b   = i >> 12;
    int  x   = i & 4095;

    const float* scan = row ? knnpoints : points;
    for (int m = t; m < 4096; m += 256) {
        float qx = scan[(b * 3 + 0) * 4096 + m];
        float qy = scan[(b * 3 + 1) * 4096 + m];
        float qz = scan[(b * 3 + 2) * 4096 + m];
        sh[m + (m >> 10)] = make_float4(qx, qy, qz, fmaf(qx, qx, fmaf(qy, qy, qz * qz)));
    }
    __syncthreads();

    const float* own = row ? points : knnpoints;
    float px = own[(b * 3 + 0) * 4096 + x];
    float py = own[(b * 3 + 1) * 4096 + x];
    float pz = own[(b * 3 + 2) * 4096 + x];
    float pe = fmaf(px, px, fmaf(py, py, pz * pz));

    float minv = 3.402823e38f;
    int   c    = 0;
    int*  mybuf = buf + (pp * 4 + q) * 32;

    int mlo = q * 1024, mhi = mlo + 1024;
    for (int m0 = mlo; m0 < mhi; m0 += 4) {
        float d2v[4];
#pragma unroll
        for (int u = 0; u < 4; u++) {
            float4 qq = sh[m0 + u + q];
            float dot = fmaf(px, qq.x, fmaf(py, qq.y, pz * qq.z));
            d2v[u] = fmaxf(fmaf(-2.0f, dot, pe + qq.w), 0.0f);
        }
        minv = fminf(minv, fminf(fminf(d2v[0], d2v[1]), fminf(d2v[2], d2v[3])));
        if (row) {
            bool p0 = d2v[0] < R2, p1 = d2v[1] < R2, p2 = d2v[2] < R2, p3 = d2v[3] < R2;
            if (p0 | p1 | p2 | p3) {            // rare path
                if (p0 && c < KK) { mybuf[c] = m0 + 0; c++; }
                if (p1 && c < KK) { mybuf[c] = m0 + 1; c++; }
                if (p2 && c < KK) { mybuf[c] = m0 + 2; c++; }
                if (p3 && c < KK) { mybuf[c] = m0 + 3; c++; }
            }
        }
    }

    // merge min over the 4 quarters (lane groups of 4 are warp-aligned)
    minv = fminf(minv, __shfl_xor_sync(0xffffffffu, minv, 1));
    minv = fminf(minv, __shfl_xor_sync(0xffffffffu, minv, 2));

    if (row) {
        int lane = t & 31, g0 = lane & ~3;
        int c0 = __shfl_sync(0xffffffffu, c, g0 + 0);
        int c1 = __shfl_sync(0xffffffffu, c, g0 + 1);
        int c2 = __shfl_sync(0xffffffffu, c, g0 + 2);
        int c3 = __shfl_sync(0xffffffffu, c, g0 + 3);
        int pre = (q > 0 ? c0 : 0) + (q > 1 ? c1 : 0) + (q > 2 ? c2 : 0);
        int tot = c0 + c1 + c2 + c3;
        int base = i * KK;
        for (int ii = 0; ii < c; ii++) {
            int pos = pre + ii;
            if (pos < KK) g_idx[base + pos] = mybuf[ii];
        }
        if (q == 0) {
            int cnt = tot < KK ? tot : KK;
            g_cnt[i] = cnt;
            if (cnt == 0) g_idx[base] = 0;   // reference fill semantics
        }
    }
    if (q == 0) red[pp] = sqrtf(1e-6f + minv);
    __syncthreads();
    if (t < 32) {
        float s = red[t] + red[t + 32];
#pragma unroll
        for (int off = 16; off > 0; off >>= 1) s += __shfl_xor_sync(0xffffffffu, s, off);
        if (t == 0) {
            if (row) g_rowpart[ib] = s;
            else     g_colpart[ib] = s;
        }
    }
}

// ---------------- fused gather + MLP + aggregate (packed f32x2) ----------------
// per-warp smem layout (floats):
//   region A [0, 680): xs[c][jp] float2, row stride 10  (c in 0..67)
//             reused as h2[o][jp] float2, row stride 10 (o in 0..63, 640 floats)
//   h1 [680, 1960): h1[o][jp] float2, row stride 10     (o in 0..127)
#define NWARP 16
#define OFF_W1 0
#define OFF_W2 8704
#define OFF_W3 16896
#define OFF_B1 20992
#define OFF_B2 21120
#define OFF_B3 21184
#define OFF_WARP 21248
#define WARP_STRIDE 1960
#define OFF_H1 680
#define SMEM_FLOATS (OFF_WARP + NWARP * WARP_STRIDE)

__global__ void __launch_bounds__(512, 1) mlp_kernel(
    const float* __restrict__ points, const float* __restrict__ knnpoints,
    const float* __restrict__ w1, const float* __restrict__ b1,
    const float* __restrict__ w2, const float* __restrict__ b2,
    const float* __restrict__ w3, const float* __restrict__ b3,
    float* __restrict__ out)
{
    extern __shared__ __align__(16) unsigned char smem_raw2[];
    float* sm = (float*)smem_raw2;
    int tid = threadIdx.x;

    // weights transposed: w?t[c][o]  (stride-1 in o -> coalesced vector loads)
    for (int e = tid; e < 128 * 68; e += 512) {
        int o = e / 68, c = e % 68;
        sm[OFF_W1 + c * 128 + o] = w1[e];
    }
    for (int e = tid; e < 64 * 128; e += 512) {
        int o = e >> 7, c = e & 127;
        sm[OFF_W2 + c * 64 + o] = w2[e];
    }
    for (int e = tid; e < 64 * 64; e += 512) {
        int o = e >> 6, c = e & 63;
        sm[OFF_W3 + c * 64 + o] = w3[e];
    }
    if (tid < 128) sm[OFF_B1 + tid] = b1[tid];
    if (tid < 64)  sm[OFF_B2 + tid] = b2[tid];
    if (tid < 64)  sm[OFF_B3 + tid] = b3[tid];
    __syncthreads();

    int lane = tid & 31;
    int wrp  = tid >> 5;
    float* ws  = sm + OFF_WARP + wrp * WARP_STRIDE;   // region A (xs / h2)
    float* h1p = ws + OFF_H1;
    const float4* w1v = (const float4*)(sm + OFF_W1);
    const float2* w2v = (const float2*)(sm + OFF_W2);
    const float2* w3v = (const float2*)(sm + OFF_W3);

    float bb1[4], bb2[2], bb3[2];
#pragma unroll
    for (int oo = 0; oo < 4; oo++) bb1[oo] = sm[OFF_B1 + 4 * lane + oo];
#pragma unroll
    for (int oo = 0; oo < 2; oo++) { bb2[oo] = sm[OFF_B2 + 2 * lane + oo];
                                     bb3[oo] = sm[OFF_B3 + 2 * lane + oo]; }

    for (;;) {
        int i = 0;
        if (lane == 0) i = (int)atomicAdd(&g_counter, 1u);
        i = __shfl_sync(0xffffffffu, i, 0);
        if (i >= Bsz * Npts) break;
        int b = i >> 12, n = i & 4095;

        float px = points[(b * 3 + 0) * 4096 + n];
        float py = points[(b * 3 + 1) * 4096 + n];
        float pz = points[(b * 3 + 2) * 4096 + n];

        int   cnt     = g_cnt[i];
        int   cols    = cnt > 0 ? cnt : 1;
        float w0extra = (float)(KK - cols + 1);   // fill column weight (exact dedup)
        int   ngroups = (cols + 7) >> 3;
        int   base    = i * KK;
        float agg0 = 0.f, agg1 = 0.f;

        for (int g = 0; g < ngroups; g++) {
            int jbase = g * 8;
            // ---- build xs[c][jp] (8 columns, packed over j-pairs) ----
            {
                int half = lane >> 4, l16 = lane & 15;
#pragma unroll
                for (int jp = 0; jp < 4; jp++) {
                    int j  = 2 * jp + half;
                    int jj = jbase + j; if (jj >= cols) jj = cols - 1;
                    int m  = g_idx[base + jj];
                    const float4* fs = (const float4*)(g_featT + ((size_t)(b * 4096 + m)) * 64);
                    float4 f = fs[l16];
                    float* dst = ws + (4 * l16) * 10 + 2 * jp + half;
                    dst[0]  = f.x;
                    dst[10] = f.y;
                    dst[20] = f.z;
                    dst[30] = f.w;
                }
                if (lane < 8) {
                    int j  = lane, jp = j >> 1, hf = j & 1;
                    int jj = jbase + j; if (jj >= cols) jj = cols - 1;
                    int m  = g_idx[base + jj];
                    float qx = knnpoints[(b * 3 + 0) * 4096 + m];
                    float qy = knnpoints[(b * 3 + 1) * 4096 + m];
                    float qz = knnpoints[(b * 3 + 2) * 4096 + m];
                    float dx = qx - px, dy = qy - py, dz = qz - pz;
                    float dd = fmaf(dx, dx, fmaf(dy, dy, dz * dz));
                    float* dst = ws + 64 * 10 + 2 * jp + hf;
                    dst[0]  = dx;
                    dst[10] = dy;
                    dst[20] = dz;
                    dst[30] = dd;
                }
            }
            __syncwarp();
            // ---- layer 1: 68 -> 128, lane owns o = 4*lane..+3, packed over jpair ----
            {
                unsigned long long acc[4][4];
#pragma unroll
                for (int jp = 0; jp < 4; jp++)
#pragma unroll
                    for (int oo = 0; oo < 4; oo++) acc[jp][oo] = packdup(bb1[oo]);
#pragma unroll
                for (int c4 = 0; c4 < 17; c4++) {
#pragma unroll
                    for (int cp = 0; cp < 2; cp++) {      // channel pairs (reg pressure)
                        float4 wA = w1v[(4 * c4 + 2 * cp + 0) * 32 + lane];
                        float4 wB = w1v[(4 * c4 + 2 * cp + 1) * 32 + lane];
                        unsigned long long wdA[4], wdB[4];
                        wdA[0] = packdup(wA.x); wdA[1] = packdup(wA.y);
                        wdA[2] = packdup(wA.z); wdA[3] = packdup(wA.w);
                        wdB[0] = packdup(wB.x); wdB[1] = packdup(wB.y);
                        wdB[2] = packdup(wB.z); wdB[3] = packdup(wB.w);
#pragma unroll
                        for (int jp = 0; jp < 4; jp++) {
                            unsigned long long xA =
                                *(const unsigned long long*)(ws + (4 * c4 + 2 * cp + 0) * 10 + 2 * jp);
                            unsigned long long xB =
                                *(const unsigned long long*)(ws + (4 * c4 + 2 * cp + 1) * 10 + 2 * jp);
#pragma unroll
                            for (int oo = 0; oo < 4; oo++) {
                                fma2(acc[jp][oo], wdA[oo], xA);
                                fma2(acc[jp][oo], wdB[oo], xB);
                            }
                        }
                    }
                }
#pragma unroll
                for (int jp = 0; jp < 4; jp++)
#pragma unroll
                    for (int oo = 0; oo < 4; oo++) {
                        float v0, v1;
                        unpack2(acc[jp][oo], v0, v1);
                        float2 r = make_float2(fmaxf(v0, 0.f), fmaxf(v1, 0.f));
                        *(float2*)(h1p + (4 * lane + oo) * 10 + 2 * jp) = r;
                    }
            }
            __syncwarp();
            // ---- layer 2: 128 -> 64, lane owns o = 2*lane, 2*lane+1 ----
            {
                unsigned long long acc[4][2];
#pragma unroll
                for (int jp = 0; jp < 4; jp++)
#pragma unroll
                    for (int oo = 0; oo < 2; oo++) acc[jp][oo] = packdup(bb2[oo]);
#pragma unroll
                for (int c4 = 0; c4 < 32; c4++) {
                    unsigned long long wd[4][2];
#pragma unroll
                    for (int cc = 0; cc < 4; cc++) {
                        float2 w = w2v[(4 * c4 + cc) * 32 + lane];
                        wd[cc][0] = packdup(w.x); wd[cc][1] = packdup(w.y);
                    }
#pragma unroll
                    for (int jp = 0; jp < 4; jp++) {
#pragma unroll
                        for (int cc = 0; cc < 4; cc++) {
                            unsigned long long xx =
                                *(const unsigned long long*)(h1p + (4 * c4 + cc) * 10 + 2 * jp);
                            fma2(acc[jp][0], wd[cc][0], xx);
                            fma2(acc[jp][1], wd[cc][1], xx);
                        }
                    }
                }
#pragma unroll
                for (int jp = 0; jp < 4; jp++)
#pragma unroll
                    for (int oo = 0; oo < 2; oo++) {
                        float v0, v1;
                        unpack2(acc[jp][oo], v0, v1);
                        float2 r = make_float2(fmaxf(v0, 0.f), fmaxf(v1, 0.f));
                        *(float2*)(ws + (2 * lane + oo) * 10 + 2 * jp) = r;  // h2 in region A
                    }
            }
            __syncwarp();
            // ---- layer 3: 64 -> 64 + aggregate ----
            {
                unsigned long long acc[4][2];
#pragma unroll
                for (int jp = 0; jp < 4; jp++)
#pragma unroll
                    for (int oo = 0; oo < 2; oo++) acc[jp][oo] = packdup(bb3[oo]);
#pragma unroll
                for (int c4 = 0; c4 < 16; c4++) {
                    unsigned long long wd[4][2];
#pragma unroll
                    for (int cc = 0; cc < 4; cc++) {
                        float2 w = w3v[(4 * c4 + cc) * 32 + lane];
                        wd[cc][0] = packdup(w.x); wd[cc][1] = packdup(w.y);
                    }
#pragma unroll
                    for (int jp = 0; jp < 4; jp++) {
#pragma unroll
                        for (int cc = 0; cc < 4; cc++) {
                            unsigned long long xx =
                                *(const unsigned long long*)(ws + (4 * c4 + cc) * 10 + 2 * jp);
                            fma2(acc[jp][0], wd[cc][0], xx);
                            fma2(acc[jp][1], wd[cc][1], xx);
                        }
                    }
                }
#pragma unroll
                for (int jp = 0; jp < 4; jp++) {
                    int j0 = jbase + 2 * jp, j1 = j0 + 1;
                    float wj0 = (j0 == 0) ? w0extra : ((j0 < cols) ? 1.0f : 0.0f);
                    float wj1 = (j1 == 0) ? w0extra : ((j1 < cols) ? 1.0f : 0.0f);
                    float v0, v1;
                    unpack2(acc[jp][0], v0, v1);
                    agg0 = fmaf(wj0, fmaxf(v0, 0.f), agg0);
                    agg0 = fmaf(wj1, fmaxf(v1, 0.f), agg0);
                    unpack2(acc[jp][1], v0, v1);
                    agg1 = fmaf(wj0, fmaxf(v0, 0.f), agg1);
                    agg1 = fmaf(wj1, fmaxf(v1, 0.f), agg1);
                }
            }
            __syncwarp();
        }
        out[((size_t)(b * 64 + 2 * lane + 0)) * 4096 + n] = agg0;
        out[((size_t)(b * 64 + 2 * lane + 1)) * 4096 + n] = agg1;
    }
}

// ---------------- deterministic final loss reduction ----------------
__global__ void loss_kernel(float* __restrict__ out, int pos) {
    int lane = threadIdx.x;
    float s = 0.f;
    for (int t = lane; t < 128; t += 32) s += g_rowpart[t] + g_colpart[t];
#pragma unroll
    for (int off = 16; off > 0; off >>= 1) s += __shfl_xor_sync(0xffffffffu, s, off);
    if (lane == 0) out[pos] = s * (1.0f / 8192.0f);
}

extern "C" void kernel_launch(void* const* d_in, const int* in_sizes, int n_in,
                              void* d_out, int out_size) {
    const float* points    = (const float*)d_in[0];
    const float* knnpoints = (const float*)d_in[1];
    const float* feat      = (const float*)d_in[2];
    const float* w1 = (const float*)d_in[3];
    const float* b1 = (const float*)d_in[4];
    const float* w2 = (const float*)d_in[5];
    const float* b2 = (const float*)d_in[6];
    const float* w3 = (const float*)d_in[7];
    const float* b3 = (const float*)d_in[8];
    float* out = (float*)d_out;

    cudaFuncSetAttribute(dist_kernel, cudaFuncAttributeMaxDynamicSharedMemorySize, DIST_SMEM);
    cudaFuncSetAttribute(mlp_kernel,  cudaFuncAttributeMaxDynamicSharedMemorySize, SMEM_FLOATS * 4);

    int nsm = 148;
    cudaDeviceGetAttribute(&nsm, cudaDevAttrMultiProcessorCount, 0);

    dim3 tb(32, 8);
    dim3 tg(Mpts / 32, CC / 32, Bsz);
    prep_kernel<<<tg, tb>>>(feat);
    dist_kernel<<<256, 256, DIST_SMEM>>>(points, knnpoints);
    mlp_kernel<<<nsm, 512, SMEM_FLOATS * 4>>>(points, knnpoints, w1, b1, w2, b2, w3, b3, out);
    loss_kernel<<<1, 32>>>(out, Bsz * 64 * Npts);
}

// round 8
// speedup vs baseline: 1.7469x; 1.1362x over previous
#include <cuda_runtime.h>
#include <math.h>

#define Bsz 2
#define Npts 4096
#define Mpts 4096
#define KK 32
#define CC 64
#define R2 0.0064f

// ---------------- device scratch (no allocs allowed) ----------------
__device__ float g_F[Bsz * Mpts * 128];      // F[b][m][o] = W1[:, :64]·feat[b,:,m] + b1
__device__ int   g_idx[Bsz * Npts * KK];     // ball query indices (compacted)
__device__ int   g_cnt[Bsz * Npts];          // neighbor counts
__device__ float g_rowpart[128];             // per-block partial sums: min over m
__device__ float g_colpart[128];             // per-block partial sums: min over n
__device__ unsigned int g_counter;           // work queue for mlp kernel

// ---------------- packed f32x2 helpers ----------------
__device__ __forceinline__ unsigned long long packdup(float a) {
    unsigned long long r;
    asm("mov.b64 %0, {%1, %1};" : "=l"(r) : "f"(a));
    return r;
}
__device__ __forceinline__ unsigned long long pack2(float a, float b) {
    unsigned long long r;
    asm("mov.b64 %0, {%1, %2};" : "=l"(r) : "f"(a), "f"(b));
    return r;
}
__device__ __forceinline__ void unpack2(unsigned long long v, float& a, float& b) {
    asm("mov.b64 {%0, %1}, %2;" : "=f"(a), "=f"(b) : "l"(v));
}
__device__ __forceinline__ void fma2(unsigned long long& d, unsigned long long a,
                                     unsigned long long b) {
    asm("fma.rn.f32x2 %0, %1, %2, %0;" : "+l"(d) : "l"(a), "l"(b));
}

// ---------------- F precompute: F[m][o] = W1f·feat[m] + b1 ----------------
// 65536 threads: og = g>>13 (o-group of 16), idx = g & 8191 -> (b, m)
__global__ void fkernel(const float* __restrict__ feat,
                        const float* __restrict__ w1,
                        const float* __restrict__ b1) {
    __shared__ float sw[64 * 128];   // [c][og][16]
    __shared__ float sb[128];
    int tid = threadIdx.x;
    if (blockIdx.x == 0 && tid == 0) g_counter = 0u;
    for (int e = tid; e < 128 * 64; e += 256) {
        int o = e >> 6, c = e & 63;
        sw[(c * 8 + (o >> 4)) * 16 + (o & 15)] = w1[o * 68 + c];
    }
    if (tid < 128) sb[tid] = b1[tid];
    __syncthreads();

    int g   = blockIdx.x * 256 + tid;
    int og  = g >> 13;
    int idx = g & 8191;
    int b   = idx >> 12, m = idx & 4095;

    unsigned long long acc[8];
    const unsigned long long* sbv = (const unsigned long long*)(sb + og * 16);
#pragma unroll
    for (int k = 0; k < 8; k++) acc[k] = sbv[k];

    const float* fp = feat + b * 64 * 4096 + m;
#pragma unroll 8
    for (int c = 0; c < 64; c++) {
        unsigned long long xd = packdup(fp[c * 4096]);
        const unsigned long long* wv = (const unsigned long long*)(sw + (c * 8 + og) * 16);
#pragma unroll
        for (int k = 0; k < 8; k++) fma2(acc[k], wv[k], xd);
    }
    float4* Fo4 = (float4*)(g_F + ((size_t)idx) * 128 + og * 16);
#pragma unroll
    for (int k = 0; k < 4; k++) {
        float a0, a1, a2, a3;
        unpack2(acc[2 * k], a0, a1);
        unpack2(acc[2 * k + 1], a2, a3);
        Fo4[k] = make_float4(a0, a1, a2, a3);
    }
}

// ---------------- distance scan: 4 threads per point ----------------
#define DIST_SMEM (4100 * 16 + 64 * 4 * 32 * 4 + 64 * 4)
__global__ void dist_kernel(const float* __restrict__ points,
                            const float* __restrict__ knnpoints) {
    extern __shared__ __align__(16) unsigned char smem_raw[];
    float4* sh  = (float4*)smem_raw;                 // 4100 entries (quarter-staggered)
    int*    buf = (int*)(sh + 4100);                 // [64][4][32] hit scratch
    float*  red = (float*)(buf + 64 * 4 * 32);       // 64-float reduction buffer

    int t  = threadIdx.x;
    bool row = blockIdx.x < 128;
    int  ib  = row ? blockIdx.x : blockIdx.x - 128;
    int  pp  = t >> 2;
    int  q   = t & 3;
    int  i   = ib * 64 + pp;
    int  b   = i >> 12;
    int  x   = i & 4095;

    const float* scan = row ? knnpoints : points;
    for (int m = t; m < 4096; m += 256) {
        float qx = scan[(b * 3 + 0) * 4096 + m];
        float qy = scan[(b * 3 + 1) * 4096 + m];
        float qz = scan[(b * 3 + 2) * 4096 + m];
        sh[m + (m >> 10)] = make_float4(qx, qy, qz, fmaf(qx, qx, fmaf(qy, qy, qz * qz)));
    }
    __syncthreads();

    const float* own = row ? points : knnpoints;
    float px = own[(b * 3 + 0) * 4096 + x];
    float py = own[(b * 3 + 1) * 4096 + x];
    float pz = own[(b * 3 + 2) * 4096 + x];
    float pe = fmaf(px, px, fmaf(py, py, pz * pz));

    float minv = 3.402823e38f;
    int   c    = 0;
    int*  mybuf = buf + (pp * 4 + q) * 32;

    int mlo = q * 1024, mhi = mlo + 1024;
    for (int m0 = mlo; m0 < mhi; m0 += 4) {
        float d2v[4];
#pragma unroll
        for (int u = 0; u < 4; u++) {
            float4 qq = sh[m0 + u + q];
            float dot = fmaf(px, qq.x, fmaf(py, qq.y, pz * qq.z));
            d2v[u] = fmaxf(fmaf(-2.0f, dot, pe + qq.w), 0.0f);
        }
        minv = fminf(minv, fminf(fminf(d2v[0], d2v[1]), fminf(d2v[2], d2v[3])));
        if (row) {
            bool p0 = d2v[0] < R2, p1 = d2v[1] < R2, p2 = d2v[2] < R2, p3 = d2v[3] < R2;
            if (p0 | p1 | p2 | p3) {
                if (p0 && c < KK) { mybuf[c] = m0 + 0; c++; }
                if (p1 && c < KK) { mybuf[c] = m0 + 1; c++; }
                if (p2 && c < KK) { mybuf[c] = m0 + 2; c++; }
                if (p3 && c < KK) { mybuf[c] = m0 + 3; c++; }
            }
        }
    }

    minv = fminf(minv, __shfl_xor_sync(0xffffffffu, minv, 1));
    minv = fminf(minv, __shfl_xor_sync(0xffffffffu, minv, 2));

    if (row) {
        int lane = t & 31, g0 = lane & ~3;
        int c0 = __shfl_sync(0xffffffffu, c, g0 + 0);
        int c1 = __shfl_sync(0xffffffffu, c, g0 + 1);
        int c2 = __shfl_sync(0xffffffffu, c, g0 + 2);
        int c3 = __shfl_sync(0xffffffffu, c, g0 + 3);
        int pre = (q > 0 ? c0 : 0) + (q > 1 ? c1 : 0) + (q > 2 ? c2 : 0);
        int tot = c0 + c1 + c2 + c3;
        int base = i * KK;
        for (int ii = 0; ii < c; ii++) {
            int pos = pre + ii;
            if (pos < KK) g_idx[base + pos] = mybuf[ii];
        }
        if (q == 0) {
            int cnt = tot < KK ? tot : KK;
            g_cnt[i] = cnt;
            if (cnt == 0) g_idx[base] = 0;
        }
    }
    if (q == 0) red[pp] = sqrtf(1e-6f + minv);
    __syncthreads();
    if (t < 32) {
        float s = red[t] + red[t + 32];
#pragma unroll
        for (int off = 16; off > 0; off >>= 1) s += __shfl_xor_sync(0xffffffffu, s, off);
        if (t == 0) {
            if (row) g_rowpart[ib] = s;
            else     g_colpart[ib] = s;
        }
    }
}

// ---------------- fused gather + MLP + aggregate (F-folded layer1) ----------------
// smem: w2t[c][o] (8192), w3t[c][o] (4096), b2(64), b3(64), then 16 warp regions.
// warp region (1600 floats): xs[64] (m idx[8] + diff[4][8]),
//   h1: 4 rows x 256 floats ([jp][o] float2, XOR-swizzled 16B units),
//   h2: 4 rows x 128 floats ([jp][o] float2, natural).
#define OFF_W2 0
#define OFF_W3 8192
#define OFF_B2 12288
#define OFF_B3 12352
#define OFF_WARP 12416
#define OFF_H1 64
#define OFF_H2 (64 + 1024)
#define WARP_STRIDE 1600
#define SMEM_FLOATS (OFF_WARP + 16 * WARP_STRIDE)

__global__ void __launch_bounds__(512, 1) mlp_kernel(
    const float* __restrict__ points, const float* __restrict__ knnpoints,
    const float* __restrict__ w1,
    const float* __restrict__ w2, const float* __restrict__ b2,
    const float* __restrict__ w3, const float* __restrict__ b3,
    float* __restrict__ out)
{
    extern __shared__ __align__(16) unsigned char smem_raw2[];
    float* sm = (float*)smem_raw2;
    int tid = threadIdx.x;

    for (int e = tid; e < 64 * 128; e += 512) {
        int o = e >> 7, c = e & 127;
        sm[OFF_W2 + c * 64 + o] = w2[e];
    }
    for (int e = tid; e < 64 * 64; e += 512) {
        int o = e >> 6, c = e & 63;
        sm[OFF_W3 + c * 64 + o] = w3[e];
    }
    if (tid < 64) sm[OFF_B2 + tid] = b2[tid];
    if (tid < 64) sm[OFF_B3 + tid] = b3[tid];
    __syncthreads();

    int lane = tid & 31;
    int wrp  = tid >> 5;
    float* ws  = sm + OFF_WARP + wrp * WARP_STRIDE;
    float* h1p = ws + OFF_H1;
    float* h2p = ws + OFF_H2;
    int*   msh = (int*)ws;
    const float2* w2v = (const float2*)(sm + OFF_W2);
    const float2* w3v = (const float2*)(sm + OFF_W3);

    // persistent packed layer-1 diff weights: wd1[ch][oo], o = 4*lane+oo
    unsigned long long wd1[4][4];
#pragma unroll
    for (int oo = 0; oo < 4; oo++)
#pragma unroll
        for (int ch = 0; ch < 4; ch++)
            wd1[ch][oo] = packdup(w1[(4 * lane + oo) * 68 + 64 + ch]);

    float bb2[2], bb3[2];
#pragma unroll
    for (int oo = 0; oo < 2; oo++) { bb2[oo] = sm[OFF_B2 + 2 * lane + oo];
                                     bb3[oo] = sm[OFF_B3 + 2 * lane + oo]; }

    for (;;) {
        int i = 0;
        if (lane == 0) i = (int)atomicAdd(&g_counter, 1u);
        i = __shfl_sync(0xffffffffu, i, 0);
        if (i >= Bsz * Npts) break;
        int b = i >> 12, n = i & 4095;

        float px = points[(b * 3 + 0) * 4096 + n];
        float py = points[(b * 3 + 1) * 4096 + n];
        float pz = points[(b * 3 + 2) * 4096 + n];

        int   cnt     = g_cnt[i];
        int   cols    = cnt > 0 ? cnt : 1;
        float w0extra = (float)(KK - cols + 1);
        int   ngroups = (cols + 7) >> 3;
        int   base    = i * KK;
        float agg0 = 0.f, agg1 = 0.f;

        for (int g = 0; g < ngroups; g++) {
            int jbase = g * 8;
            // ---- build: m indices + diff channels ----
            if (lane < 8) {
                int j  = lane;
                int jj = jbase + j; if (jj >= cols) jj = cols - 1;
                int m  = g_idx[base + jj];
                msh[j] = m;
                float qx = knnpoints[(b * 3 + 0) * 4096 + m];
                float qy = knnpoints[(b * 3 + 1) * 4096 + m];
                float qz = knnpoints[(b * 3 + 2) * 4096 + m];
                float dx = qx - px, dy = qy - py, dz = qz - pz;
                float dd = fmaf(dx, dx, fmaf(dy, dy, dz * dz));
                ws[8 + 0 * 8 + j] = dx;
                ws[8 + 1 * 8 + j] = dy;
                ws[8 + 2 * 8 + j] = dz;
                ws[8 + 3 * 8 + j] = dd;
            }
            __syncwarp();
            // ---- layer 1: F[m] + W1d·diff (4 channels), o = 4lane..+3 ----
            {
                float4 Fv[8];
#pragma unroll
                for (int j = 0; j < 8; j++) {
                    int m = msh[j];
                    Fv[j] = *(const float4*)(g_F + ((size_t)((b << 12) + m)) * 128 + 4 * lane);
                }
                unsigned long long xch[4][4];
#pragma unroll
                for (int ch = 0; ch < 4; ch++)
#pragma unroll
                    for (int jp = 0; jp < 4; jp++)
                        xch[ch][jp] = *(const unsigned long long*)(ws + 8 + ch * 8 + 2 * jp);

                unsigned long long acc[4][4];
#pragma unroll
                for (int jp = 0; jp < 4; jp++) {
                    acc[jp][0] = pack2(Fv[2 * jp].x, Fv[2 * jp + 1].x);
                    acc[jp][1] = pack2(Fv[2 * jp].y, Fv[2 * jp + 1].y);
                    acc[jp][2] = pack2(Fv[2 * jp].z, Fv[2 * jp + 1].z);
                    acc[jp][3] = pack2(Fv[2 * jp].w, Fv[2 * jp + 1].w);
                }
#pragma unroll
                for (int ch = 0; ch < 4; ch++)
#pragma unroll
                    for (int jp = 0; jp < 4; jp++)
#pragma unroll
                        for (int oo = 0; oo < 4; oo++)
                            fma2(acc[jp][oo], wd1[ch][oo], xch[ch][jp]);

                int u0 = 2 * lane, u1 = 2 * lane + 1;
                int p0 = u0 ^ ((u0 >> 3) & 7);
                int p1 = u1 ^ ((u1 >> 3) & 7);
#pragma unroll
                for (int jp = 0; jp < 4; jp++) {
                    float v0, v1, v2, v3;
                    unpack2(acc[jp][0], v0, v1);
                    unpack2(acc[jp][1], v2, v3);
                    *(float4*)(h1p + jp * 256 + p0 * 4) =
                        make_float4(fmaxf(v0, 0.f), fmaxf(v1, 0.f), fmaxf(v2, 0.f), fmaxf(v3, 0.f));
                    unpack2(acc[jp][2], v0, v1);
                    unpack2(acc[jp][3], v2, v3);
                    *(float4*)(h1p + jp * 256 + p1 * 4) =
                        make_float4(fmaxf(v0, 0.f), fmaxf(v1, 0.f), fmaxf(v2, 0.f), fmaxf(v3, 0.f));
                }
            }
            __syncwarp();
            // ---- layer 2: 128 -> 64, lane owns o = 2lane, 2lane+1 ----
            {
                unsigned long long acc[4][2];
#pragma unroll
                for (int jp = 0; jp < 4; jp++) {
                    acc[jp][0] = packdup(bb2[0]);
                    acc[jp][1] = packdup(bb2[1]);
                }
#pragma unroll
                for (int c4 = 0; c4 < 32; c4++) {
                    unsigned long long wd[4][2];
#pragma unroll
                    for (int cc = 0; cc < 4; cc++) {
                        float2 w = w2v[(4 * c4 + cc) * 32 + lane];
                        wd[cc][0] = packdup(w.x); wd[cc][1] = packdup(w.y);
                    }
                    int ua = 2 * c4, ub = 2 * c4 + 1;
                    int pa = ua ^ ((ua >> 3) & 7);
                    int pb = ub ^ ((ub >> 3) & 7);
#pragma unroll
                    for (int jp = 0; jp < 4; jp++) {
                        ulonglong2 XA = *(const ulonglong2*)(h1p + jp * 256 + pa * 4);
                        ulonglong2 XB = *(const ulonglong2*)(h1p + jp * 256 + pb * 4);
                        fma2(acc[jp][0], wd[0][0], XA.x); fma2(acc[jp][1], wd[0][1], XA.x);
                        fma2(acc[jp][0], wd[1][0], XA.y); fma2(acc[jp][1], wd[1][1], XA.y);
                        fma2(acc[jp][0], wd[2][0], XB.x); fma2(acc[jp][1], wd[2][1], XB.x);
                        fma2(acc[jp][0], wd[3][0], XB.y); fma2(acc[jp][1], wd[3][1], XB.y);
                    }
                }
#pragma unroll
                for (int jp = 0; jp < 4; jp++) {
                    float v0, v1, v2, v3;
                    unpack2(acc[jp][0], v0, v1);
                    unpack2(acc[jp][1], v2, v3);
                    *(float4*)(h2p + jp * 128 + 4 * lane) =
                        make_float4(fmaxf(v0, 0.f), fmaxf(v1, 0.f), fmaxf(v2, 0.f), fmaxf(v3, 0.f));
                }
            }
            __syncwarp();
            // ---- layer 3: 64 -> 64 + aggregate ----
            {
                unsigned long long acc[4][2];
#pragma unroll
                for (int jp = 0; jp < 4; jp++) {
                    acc[jp][0] = packdup(bb3[0]);
                    acc[jp][1] = packdup(bb3[1]);
                }
#pragma unroll
                for (int c4 = 0; c4 < 16; c4++) {
                    unsigned long long wd[4][2];
#pragma unroll
                    for (int cc = 0; cc < 4; cc++) {
                        float2 w = w3v[(4 * c4 + cc) * 32 + lane];
                        wd[cc][0] = packdup(w.x); wd[cc][1] = packdup(w.y);
                    }
#pragma unroll
                    for (int jp = 0; jp < 4; jp++) {
                        ulonglong2 XA = *(const ulonglong2*)(h2p + jp * 128 + 8 * c4);
                        ulonglong2 XB = *(const ulonglong2*)(h2p + jp * 128 + 8 * c4 + 4);
                        fma2(acc[jp][0], wd[0][0], XA.x); fma2(acc[jp][1], wd[0][1], XA.x);
                        fma2(acc[jp][0], wd[1][0], XA.y); fma2(acc[jp][1], wd[1][1], XA.y);
                        fma2(acc[jp][0], wd[2][0], XB.x); fma2(acc[jp][1], wd[2][1], XB.x);
                        fma2(acc[jp][0], wd[3][0], XB.y); fma2(acc[jp][1], wd[3][1], XB.y);
                    }
                }
#pragma unroll
                for (int jp = 0; jp < 4; jp++) {
                    int j0 = jbase + 2 * jp, j1 = j0 + 1;
                    float wj0 = (j0 == 0) ? w0extra : ((j0 < cols) ? 1.0f : 0.0f);
                    float wj1 = (j1 == 0) ? w0extra : ((j1 < cols) ? 1.0f : 0.0f);
                    float v0, v1;
                    unpack2(acc[jp][0], v0, v1);
                    agg0 = fmaf(wj0, fmaxf(v0, 0.f), agg0);
                    agg0 = fmaf(wj1, fmaxf(v1, 0.f), agg0);
                    unpack2(acc[jp][1], v0, v1);
                    agg1 = fmaf(wj0, fmaxf(v0, 0.f), agg1);
                    agg1 = fmaf(wj1, fmaxf(v1, 0.f), agg1);
                }
            }
            __syncwarp();
        }
        out[((size_t)(b * 64 + 2 * lane + 0)) * 4096 + n] = agg0;
        out[((size_t)(b * 64 + 2 * lane + 1)) * 4096 + n] = agg1;
    }

    // ---- folded loss reduction (depends only on dist_kernel results) ----
    if (blockIdx.x == 0 && tid < 32) {
        float s = 0.f;
        for (int t = tid; t < 128; t += 32) s += g_rowpart[t] + g_colpart[t];
#pragma unroll
        for (int off = 16; off > 0; off >>= 1) s += __shfl_xor_sync(0xffffffffu, s, off);
        if (tid == 0) out[Bsz * 64 * Npts] = s * (1.0f / 8192.0f);
    }
}

extern "C" void kernel_launch(void* const* d_in, const int* in_sizes, int n_in,
                              void* d_out, int out_size) {
    const float* points    = (const float*)d_in[0];
    const float* knnpoints = (const float*)d_in[1];
    const float* feat      = (const float*)d_in[2];
    const float* w1 = (const float*)d_in[3];
    const float* b1 = (const float*)d_in[4];
    const float* w2 = (const float*)d_in[5];
    const float* b2 = (const float*)d_in[6];
    const float* w3 = (const float*)d_in[7];
    const float* b3 = (const float*)d_in[8];
    float* out = (float*)d_out;

    cudaFuncSetAttribute(dist_kernel, cudaFuncAttributeMaxDynamicSharedMemorySize, DIST_SMEM);
    cudaFuncSetAttribute(mlp_kernel,  cudaFuncAttributeMaxDynamicSharedMemorySize, SMEM_FLOATS * 4);

    int nsm = 148;
    cudaDeviceGetAttribute(&nsm, cudaDevAttrMultiProcessorCount, 0);

    fkernel<<<256, 256>>>(feat, w1, b1);
    dist_kernel<<<256, 256, DIST_SMEM>>>(points, knnpoints);
    mlp_kernel<<<nsm, 512, SMEM_FLOATS * 4>>>(points, knnpoints, w1, w2, b2, w3, b3, out);
}

// round 9
// speedup vs baseline: 1.9275x; 1.1034x over previous
#include <cuda_runtime.h>
#include <math.h>

#define Bsz 2
#define Npts 4096
#define Mpts 4096
#define KK 32
#define CC 64
#define R2 0.0064f

// ---------------- device scratch (no allocs allowed) ----------------
__device__ float g_F[Bsz * Mpts * 128];      // F[b][m][o] = W1[:, :64]·feat[b,:,m] + b1
__device__ int   g_idx[Bsz * Npts * KK];     // ball query indices (compacted)
__device__ int   g_cnt[Bsz * Npts];          // neighbor counts
__device__ float g_rowpart[128];             // per-block partial sums: min over m
__device__ float g_colpart[128];             // per-block partial sums: min over n
__device__ unsigned int g_counter;           // work queue for mlp kernel

// ---------------- packed f32x2 helpers ----------------
__device__ __forceinline__ unsigned long long packdup(float a) {
    unsigned long long r;
    asm("mov.b64 %0, {%1, %1};" : "=l"(r) : "f"(a));
    return r;
}
__device__ __forceinline__ unsigned long long pack2(float a, float b) {
    unsigned long long r;
    asm("mov.b64 %0, {%1, %2};" : "=l"(r) : "f"(a), "f"(b));
    return r;
}
__device__ __forceinline__ void unpack2(unsigned long long v, float& a, float& b) {
    asm("mov.b64 {%0, %1}, %2;" : "=f"(a), "=f"(b) : "l"(v));
}
__device__ __forceinline__ void fma2(unsigned long long& d, unsigned long long a,
                                     unsigned long long b) {
    asm("fma.rn.f32x2 %0, %1, %2, %0;" : "+l"(d) : "l"(a), "l"(b));
}

// ---------------- fused distance scan + F precompute ----------------
// blocks [0,128): dist row task (per n: ball query + min over m)
// blocks [128,256): dist col task (per m: min over n)
// blocks [256,288): F GEMM blocks (each: 256 m-values x all 128 outputs)
#define DIST_SMEM (4100 * 16 + 64 * 4 * 32 * 4 + 64 * 4)
__global__ void __launch_bounds__(256, 2) distf_kernel(
    const float* __restrict__ points, const float* __restrict__ knnpoints,
    const float* __restrict__ feat, const float* __restrict__ w1,
    const float* __restrict__ b1)
{
    extern __shared__ __align__(16) unsigned char smem_raw[];
    int t = threadIdx.x;

    if (blockIdx.x >= 256) {
        // ================= F precompute path =================
        // F[idx][o] = sum_c w1[o][c]*feat[b][c][m] + b1[o],  idx = b*4096+m
        float* sw = (float*)smem_raw;     // [ (c*8+og)*16 + o16 ]  8192 floats
        float* sb = sw + 8192;            // 128 floats
        int fbid = blockIdx.x - 256;      // 0..31
        if (fbid == 0 && t == 0) g_counter = 0u;
        for (int e = t; e < 8192; e += 256) {
            int o = e >> 6, c = e & 63;
            sw[(c * 8 + (o >> 4)) * 16 + (o & 15)] = w1[o * 68 + c];
        }
        if (t < 128) sb[t] = b1[t];
        __syncthreads();

        int og   = t >> 5;                // warp id = o-group (16 outputs)
        int lane = t & 31;
        const unsigned long long* sbv = (const unsigned long long*)(sb + og * 16);
        int idx_base = fbid * 256;
        int b     = idx_base >> 12;
        int mbase = idx_base & 4095;
        const float* fb = feat + ((size_t)b * 64) * 4096;

#pragma unroll
        for (int it = 0; it < 2; it++) {
            int mloc = it * 128 + lane * 4;
            unsigned long long acc[4][8];
#pragma unroll
            for (int mi = 0; mi < 4; mi++)
#pragma unroll
                for (int k = 0; k < 8; k++) acc[mi][k] = sbv[k];

            const float* fp = fb + mbase + mloc;
#pragma unroll 8
            for (int c = 0; c < 64; c++) {
                float4 f4 = *(const float4*)(fp + c * 4096);
                const unsigned long long* wv =
                    (const unsigned long long*)(sw + (c * 8 + og) * 16);
                unsigned long long x0 = packdup(f4.x), x1 = packdup(f4.y);
                unsigned long long x2 = packdup(f4.z), x3 = packdup(f4.w);
#pragma unroll
                for (int k = 0; k < 8; k++) {
                    unsigned long long w = wv[k];
                    fma2(acc[0][k], w, x0);
                    fma2(acc[1][k], w, x1);
                    fma2(acc[2][k], w, x2);
                    fma2(acc[3][k], w, x3);
                }
            }
#pragma unroll
            for (int mi = 0; mi < 4; mi++) {
                float4* dst = (float4*)(g_F + ((size_t)(idx_base + mloc + mi)) * 128 + og * 16);
#pragma unroll
                for (int k = 0; k < 4; k++) {
                    float a0, a1, a2, a3;
                    unpack2(acc[mi][2 * k], a0, a1);
                    unpack2(acc[mi][2 * k + 1], a2, a3);
                    dst[k] = make_float4(a0, a1, a2, a3);
                }
            }
        }
        return;
    }

    // ================= distance path =================
    float4* sh  = (float4*)smem_raw;                 // 4100 entries (quarter-staggered)
    int*    buf = (int*)(sh + 4100);                 // [64][4][32] hit scratch
    float*  red = (float*)(buf + 64 * 4 * 32);       // 64-float reduction buffer

    bool row = blockIdx.x < 128;
    int  ib  = row ? blockIdx.x : blockIdx.x - 128;
    int  pp  = t >> 2;
    int  q   = t & 3;
    int  i   = ib * 64 + pp;
    int  b   = i >> 12;
    int  x   = i & 4095;

    const float* scan = row ? knnpoints : points;
    for (int m = t; m < 4096; m += 256) {
        float qx = scan[(b * 3 + 0) * 4096 + m];
        float qy = scan[(b * 3 + 1) * 4096 + m];
        float qz = scan[(b * 3 + 2) * 4096 + m];
        sh[m + (m >> 10)] = make_float4(qx, qy, qz, fmaf(qx, qx, fmaf(qy, qy, qz * qz)));
    }
    __syncthreads();

    const float* own = row ? points : knnpoints;
    float px = own[(b * 3 + 0) * 4096 + x];
    float py = own[(b * 3 + 1) * 4096 + x];
    float pz = own[(b * 3 + 2) * 4096 + x];
    float pe = fmaf(px, px, fmaf(py, py, pz * pz));

    float minv = 3.402823e38f;
    int   c    = 0;
    int*  mybuf = buf + (pp * 4 + q) * 32;

    int mlo = q * 1024, mhi = mlo + 1024;
    for (int m0 = mlo; m0 < mhi; m0 += 4) {
        float d2v[4];
#pragma unroll
        for (int u = 0; u < 4; u++) {
            float4 qq = sh[m0 + u + q];
            float dot = fmaf(px, qq.x, fmaf(py, qq.y, pz * qq.z));
            d2v[u] = fmaxf(fmaf(-2.0f, dot, pe + qq.w), 0.0f);
        }
        minv = fminf(minv, fminf(fminf(d2v[0], d2v[1]), fminf(d2v[2], d2v[3])));
        if (row) {
            bool p0 = d2v[0] < R2, p1 = d2v[1] < R2, p2 = d2v[2] < R2, p3 = d2v[3] < R2;
            if (p0 | p1 | p2 | p3) {
                if (p0 && c < KK) { mybuf[c] = m0 + 0; c++; }
                if (p1 && c < KK) { mybuf[c] = m0 + 1; c++; }
                if (p2 && c < KK) { mybuf[c] = m0 + 2; c++; }
                if (p3 && c < KK) { mybuf[c] = m0 + 3; c++; }
            }
        }
    }

    minv = fminf(minv, __shfl_xor_sync(0xffffffffu, minv, 1));
    minv = fminf(minv, __shfl_xor_sync(0xffffffffu, minv, 2));

    if (row) {
        int lane = t & 31, g0 = lane & ~3;
        int c0 = __shfl_sync(0xffffffffu, c, g0 + 0);
        int c1 = __shfl_sync(0xffffffffu, c, g0 + 1);
        int c2 = __shfl_sync(0xffffffffu, c, g0 + 2);
        int c3 = __shfl_sync(0xffffffffu, c, g0 + 3);
        int pre = (q > 0 ? c0 : 0) + (q > 1 ? c1 : 0) + (q > 2 ? c2 : 0);
        int tot = c0 + c1 + c2 + c3;
        int base = i * KK;
        for (int ii = 0; ii < c; ii++) {
            int pos = pre + ii;
            if (pos < KK) g_idx[base + pos] = mybuf[ii];
        }
        if (q == 0) {
            int cnt = tot < KK ? tot : KK;
            g_cnt[i] = cnt;
            if (cnt == 0) g_idx[base] = 0;
        }
    }
    if (q == 0) red[pp] = sqrtf(1e-6f + minv);
    __syncthreads();
    if (t < 32) {
        float s = red[t] + red[t + 32];
#pragma unroll
        for (int off = 16; off > 0; off >>= 1) s += __shfl_xor_sync(0xffffffffu, s, off);
        if (t == 0) {
            if (row) g_rowpart[ib] = s;
            else     g_colpart[ib] = s;
        }
    }
}

// ---------------- fused gather + MLP + aggregate (F-folded layer1) ----------------
#define OFF_W2 0
#define OFF_W3 8192
#define OFF_B2 12288
#define OFF_B3 12352
#define OFF_WARP 12416
#define OFF_H1 64
#define OFF_H2 (64 + 1024)
#define WARP_STRIDE 1600
#define SMEM_FLOATS (OFF_WARP + 16 * WARP_STRIDE)

// One neighbor-column group of 2*NJP columns (NJP=4 -> 8 cols, NJP=2 -> 4 cols).
template <int NJP>
__device__ __forceinline__ void mlp_group(
    float* ws, float* h1p, float* h2p, int* msh,
    const float2* w2v, const float2* w3v,
    const unsigned long long (&wd1)[4][4],
    float bb2_0, float bb2_1, float bb3_0, float bb3_1,
    const float* __restrict__ knnpoints, int b, int lane,
    int jbase, int cols, float w0extra,
    float px, float py, float pz, int base,
    float& agg0, float& agg1)
{
    // ---- build: m indices + diff channels ----
    if (lane < 2 * NJP) {
        int j  = lane;
        int jj = jbase + j; if (jj >= cols) jj = cols - 1;
        int m  = g_idx[base + jj];
        msh[j] = m;
        float qx = knnpoints[(b * 3 + 0) * 4096 + m];
        float qy = knnpoints[(b * 3 + 1) * 4096 + m];
        float qz = knnpoints[(b * 3 + 2) * 4096 + m];
        float dx = qx - px, dy = qy - py, dz = qz - pz;
        float dd = fmaf(dx, dx, fmaf(dy, dy, dz * dz));
        ws[8 + 0 * 8 + j] = dx;
        ws[8 + 1 * 8 + j] = dy;
        ws[8 + 2 * 8 + j] = dz;
        ws[8 + 3 * 8 + j] = dd;
    }
    __syncwarp();
    // ---- layer 1: F[m] + W1d·diff (4 channels), o = 4lane..+3 ----
    {
        float4 Fv[2 * NJP];
#pragma unroll
        for (int j = 0; j < 2 * NJP; j++) {
            int m = msh[j];
            Fv[j] = *(const float4*)(g_F + ((size_t)((b << 12) + m)) * 128 + 4 * lane);
        }
        unsigned long long xch[4][NJP];
#pragma unroll
        for (int ch = 0; ch < 4; ch++)
#pragma unroll
            for (int jp = 0; jp < NJP; jp++)
                xch[ch][jp] = *(const unsigned long long*)(ws + 8 + ch * 8 + 2 * jp);

        unsigned long long acc[NJP][4];
#pragma unroll
        for (int jp = 0; jp < NJP; jp++) {
            acc[jp][0] = pack2(Fv[2 * jp].x, Fv[2 * jp + 1].x);
            acc[jp][1] = pack2(Fv[2 * jp].y, Fv[2 * jp + 1].y);
            acc[jp][2] = pack2(Fv[2 * jp].z, Fv[2 * jp + 1].z);
            acc[jp][3] = pack2(Fv[2 * jp].w, Fv[2 * jp + 1].w);
        }
#pragma unroll
        for (int ch = 0; ch < 4; ch++)
#pragma unroll
            for (int jp = 0; jp < NJP; jp++)
#pragma unroll
                for (int oo = 0; oo < 4; oo++)
                    fma2(acc[jp][oo], wd1[ch][oo], xch[ch][jp]);

        int u0 = 2 * lane, u1 = 2 * lane + 1;
        int p0 = u0 ^ ((u0 >> 3) & 7);
        int p1 = u1 ^ ((u1 >> 3) & 7);
#pragma unroll
        for (int jp = 0; jp < NJP; jp++) {
            float v0, v1, v2, v3;
            unpack2(acc[jp][0], v0, v1);
            unpack2(acc[jp][1], v2, v3);
            *(float4*)(h1p + jp * 256 + p0 * 4) =
                make_float4(fmaxf(v0, 0.f), fmaxf(v1, 0.f), fmaxf(v2, 0.f), fmaxf(v3, 0.f));
            unpack2(acc[jp][2], v0, v1);
            unpack2(acc[jp][3], v2, v3);
            *(float4*)(h1p + jp * 256 + p1 * 4) =
                make_float4(fmaxf(v0, 0.f), fmaxf(v1, 0.f), fmaxf(v2, 0.f), fmaxf(v3, 0.f));
        }
    }
    __syncwarp();
    // ---- layer 2: 128 -> 64, lane owns o = 2lane, 2lane+1 ----
    {
        unsigned long long acc[NJP][2];
#pragma unroll
        for (int jp = 0; jp < NJP; jp++) {
            acc[jp][0] = packdup(bb2_0);
            acc[jp][1] = packdup(bb2_1);
        }
#pragma unroll
        for (int c4 = 0; c4 < 32; c4++) {
            unsigned long long wd[4][2];
#pragma unroll
            for (int cc = 0; cc < 4; cc++) {
                float2 w = w2v[(4 * c4 + cc) * 32 + lane];
                wd[cc][0] = packdup(w.x); wd[cc][1] = packdup(w.y);
            }
            int ua = 2 * c4, ub = 2 * c4 + 1;
            int pa = ua ^ ((ua >> 3) & 7);
            int pb = ub ^ ((ub >> 3) & 7);
#pragma unroll
            for (int jp = 0; jp < NJP; jp++) {
                ulonglong2 XA = *(const ulonglong2*)(h1p + jp * 256 + pa * 4);
                ulonglong2 XB = *(const ulonglong2*)(h1p + jp * 256 + pb * 4);
                fma2(acc[jp][0], wd[0][0], XA.x); fma2(acc[jp][1], wd[0][1], XA.x);
                fma2(acc[jp][0], wd[1][0], XA.y); fma2(acc[jp][1], wd[1][1], XA.y);
                fma2(acc[jp][0], wd[2][0], XB.x); fma2(acc[jp][1], wd[2][1], XB.x);
                fma2(acc[jp][0], wd[3][0], XB.y); fma2(acc[jp][1], wd[3][1], XB.y);
            }
        }
#pragma unroll
        for (int jp = 0; jp < NJP; jp++) {
            float v0, v1, v2, v3;
            unpack2(acc[jp][0], v0, v1);
            unpack2(acc[jp][1], v2, v3);
            *(float4*)(h2p + jp * 128 + 4 * lane) =
                make_float4(fmaxf(v0, 0.f), fmaxf(v1, 0.f), fmaxf(v2, 0.f), fmaxf(v3, 0.f));
        }
    }
    __syncwarp();
    // ---- layer 3: 64 -> 64 + aggregate ----
    {
        unsigned long long acc[NJP][2];
#pragma unroll
        for (int jp = 0; jp < NJP; jp++) {
            acc[jp][0] = packdup(bb3_0);
            acc[jp][1] = packdup(bb3_1);
        }
#pragma unroll
        for (int c4 = 0; c4 < 16; c4++) {
            unsigned long long wd[4][2];
#pragma unroll
            for (int cc = 0; cc < 4; cc++) {
                float2 w = w3v[(4 * c4 + cc) * 32 + lane];
                wd[cc][0] = packdup(w.x); wd[cc][1] = packdup(w.y);
            }
#pragma unroll
            for (int jp = 0; jp < NJP; jp++) {
                ulonglong2 XA = *(const ulonglong2*)(h2p + jp * 128 + 8 * c4);
                ulonglong2 XB = *(const ulonglong2*)(h2p + jp * 128 + 8 * c4 + 4);
                fma2(acc[jp][0], wd[0][0], XA.x); fma2(acc[jp][1], wd[0][1], XA.x);
                fma2(acc[jp][0], wd[1][0], XA.y); fma2(acc[jp][1], wd[1][1], XA.y);
                fma2(acc[jp][0], wd[2][0], XB.x); fma2(acc[jp][1], wd[2][1], XB.x);
                fma2(acc[jp][0], wd[3][0], XB.y); fma2(acc[jp][1], wd[3][1], XB.y);
            }
        }
#pragma unroll
        for (int jp = 0; jp < NJP; jp++) {
            int j0 = jbase + 2 * jp, j1 = j0 + 1;
            float wj0 = (j0 == 0) ? w0extra : ((j0 < cols) ? 1.0f : 0.0f);
            float wj1 = (j1 == 0) ? w0extra : ((j1 < cols) ? 1.0f : 0.0f);
            float v0, v1;
            unpack2(acc[jp][0], v0, v1);
            agg0 = fmaf(wj0, fmaxf(v0, 0.f), agg0);
            agg0 = fmaf(wj1, fmaxf(v1, 0.f), agg0);
            unpack2(acc[jp][1], v0, v1);
            agg1 = fmaf(wj0, fmaxf(v0, 0.f), agg1);
            agg1 = fmaf(wj1, fmaxf(v1, 0.f), agg1);
        }
    }
    __syncwarp();
}

__global__ void __launch_bounds__(512, 1) mlp_kernel(
    const float* __restrict__ points, const float* __restrict__ knnpoints,
    const float* __restrict__ w1,
    const float* __restrict__ w2, const float* __restrict__ b2,
    const float* __restrict__ w3, const float* __restrict__ b3,
    float* __restrict__ out)
{
    extern __shared__ __align__(16) unsigned char smem_raw2[];
    float* sm = (float*)smem_raw2;
    int tid = threadIdx.x;

    for (int e = tid; e < 64 * 128; e += 512) {
        int o = e >> 7, c = e & 127;
        sm[OFF_W2 + c * 64 + o] = w2[e];
    }
    for (int e = tid; e < 64 * 64; e += 512) {
        int o = e >> 6, c = e & 63;
        sm[OFF_W3 + c * 64 + o] = w3[e];
    }
    if (tid < 64) sm[OFF_B2 + tid] = b2[tid];
    if (tid < 64) sm[OFF_B3 + tid] = b3[tid];
    __syncthreads();

    int lane = tid & 31;
    int wrp  = tid >> 5;
    float* ws  = sm + OFF_WARP + wrp * WARP_STRIDE;
    float* h1p = ws + OFF_H1;
    float* h2p = ws + OFF_H2;
    int*   msh = (int*)ws;
    const float2* w2v = (const float2*)(sm + OFF_W2);
    const float2* w3v = (const float2*)(sm + OFF_W3);

    unsigned long long wd1[4][4];
#pragma unroll
    for (int oo = 0; oo < 4; oo++)
#pragma unroll
        for (int ch = 0; ch < 4; ch++)
            wd1[ch][oo] = packdup(w1[(4 * lane + oo) * 68 + 64 + ch]);

    float bb2_0 = sm[OFF_B2 + 2 * lane], bb2_1 = sm[OFF_B2 + 2 * lane + 1];
    float bb3_0 = sm[OFF_B3 + 2 * lane], bb3_1 = sm[OFF_B3 + 2 * lane + 1];

    for (;;) {
        int i = 0;
        if (lane == 0) i = (int)atomicAdd(&g_counter, 1u);
        i = __shfl_sync(0xffffffffu, i, 0);
        if (i >= Bsz * Npts) break;
        int b = i >> 12, n = i & 4095;

        float px = points[(b * 3 + 0) * 4096 + n];
        float py = points[(b * 3 + 1) * 4096 + n];
        float pz = points[(b * 3 + 2) * 4096 + n];

        int   cnt     = g_cnt[i];
        int   cols    = cnt > 0 ? cnt : 1;
        float w0extra = (float)(KK - cols + 1);
        int   base    = i * KK;
        float agg0 = 0.f, agg1 = 0.f;

        int jb = 0;
        while (jb < cols) {
            if (cols - jb > 4) {
                mlp_group<4>(ws, h1p, h2p, msh, w2v, w3v, wd1,
                             bb2_0, bb2_1, bb3_0, bb3_1, knnpoints, b, lane,
                             jb, cols, w0extra, px, py, pz, base, agg0, agg1);
                jb += 8;
            } else {
                mlp_group<2>(ws, h1p, h2p, msh, w2v, w3v, wd1,
                             bb2_0, bb2_1, bb3_0, bb3_1, knnpoints, b, lane,
                             jb, cols, w0extra, px, py, pz, base, agg0, agg1);
                jb += 4;
            }
        }

        out[((size_t)(b * 64 + 2 * lane + 0)) * 4096 + n] = agg0;
        out[((size_t)(b * 64 + 2 * lane + 1)) * 4096 + n] = agg1;
    }

    // ---- folded loss reduction (depends only on dist results) ----
    if (blockIdx.x == 0 && tid < 32) {
        float s = 0.f;
        for (int t = tid; t < 128; t += 32) s += g_rowpart[t] + g_colpart[t];
#pragma unroll
        for (int off = 16; off > 0; off >>= 1) s += __shfl_xor_sync(0xffffffffu, s, off);
        if (tid == 0) out[Bsz * 64 * Npts] = s * (1.0f / 8192.0f);
    }
}

extern "C" void kernel_launch(void* const* d_in, const int* in_sizes, int n_in,
                              void* d_out, int out_size) {
    const float* points    = (const float*)d_in[0];
    const float* knnpoints = (const float*)d_in[1];
    const float* feat      = (const float*)d_in[2];
    const float* w1 = (const float*)d_in[3];
    const float* b1 = (const float*)d_in[4];
    const float* w2 = (const float*)d_in[5];
    const float* b2 = (const float*)d_in[6];
    const float* w3 = (const float*)d_in[7];
    const float* b3 = (const float*)d_in[8];
    float* out = (float*)d_out;

    cudaFuncSetAttribute(distf_kernel, cudaFuncAttributeMaxDynamicSharedMemorySize, DIST_SMEM);
    cudaFuncSetAttribute(mlp_kernel,   cudaFuncAttributeMaxDynamicSharedMemorySize, SMEM_FLOATS * 4);

    int nsm = 148;
    cudaDeviceGetAttribute(&nsm, cudaDevAttrMultiProcessorCount, 0);

    distf_kernel<<<288, 256, DIST_SMEM>>>(points, knnpoints, feat, w1, b1);
    mlp_kernel<<<nsm, 512, SMEM_FLOATS * 4>>>(points, knnpoints, w1, w2, b2, w3, b3, out);
}

// round 10
// speedup vs baseline: 2.1447x; 1.1127x over previous
#include <cuda_runtime.h>
#include <math.h>

#define Bsz 2
#define Npts 4096
#define Mpts 4096
#define KK 32
#define CC 64
#define R2 0.0064f

// ---------------- device scratch (no allocs allowed) ----------------
__device__ float g_F[Bsz * Mpts * 128];      // F[b][m][o] = W1[:, :64]·feat[b,:,m] + b1
__device__ int   g_idx[Bsz * Npts * KK];     // ball query indices (compacted)
__device__ int   g_cnt[Bsz * Npts];          // neighbor counts
__device__ float g_rowpart[128];             // per-block partial sums: min over m
__device__ float g_colpart[128];             // per-block partial sums: min over n
__device__ unsigned int g_counter;           // work queue for mlp kernel

// ---------------- packed f32x2 helpers ----------------
__device__ __forceinline__ unsigned long long packdup(float a) {
    unsigned long long r;
    asm("mov.b64 %0, {%1, %1};" : "=l"(r) : "f"(a));
    return r;
}
__device__ __forceinline__ unsigned long long pack2(float a, float b) {
    unsigned long long r;
    asm("mov.b64 %0, {%1, %2};" : "=l"(r) : "f"(a), "f"(b));
    return r;
}
__device__ __forceinline__ void unpack2(unsigned long long v, float& a, float& b) {
    asm("mov.b64 {%0, %1}, %2;" : "=f"(a), "=f"(b) : "l"(v));
}
__device__ __forceinline__ void fma2(unsigned long long& d, unsigned long long a,
                                     unsigned long long b) {
    asm("fma.rn.f32x2 %0, %1, %2, %0;" : "+l"(d) : "l"(a), "l"(b));
}

// ---------------- fused distance scan + F precompute ----------------
// blocks [0,128): dist row task (per n: ball query + min over m)
// blocks [128,256): dist col task (per m: min over n)
// blocks [256,288): F GEMM blocks (each: 256 m-values x all 128 outputs)
#define DIST_SMEM (4100 * 16 + 64 * 4 * 32 * 4 + 64 * 4)
__global__ void __launch_bounds__(256, 2) distf_kernel(
    const float* __restrict__ points, const float* __restrict__ knnpoints,
    const float* __restrict__ feat, const float* __restrict__ w1,
    const float* __restrict__ b1)
{
    extern __shared__ __align__(16) unsigned char smem_raw[];
    int t = threadIdx.x;

    if (blockIdx.x >= 256) {
        // ================= F precompute path =================
        float* sw = (float*)smem_raw;     // 8192 floats
        float* sb = sw + 8192;            // 128 floats
        int fbid = blockIdx.x - 256;      // 0..31
        if (fbid == 0 && t == 0) g_counter = 0u;
        for (int e = t; e < 8192; e += 256) {
            int o = e >> 6, c = e & 63;
            sw[(c * 8 + (o >> 4)) * 16 + (o & 15)] = w1[o * 68 + c];
        }
        if (t < 128) sb[t] = b1[t];
        __syncthreads();

        int og   = t >> 5;
        int lane = t & 31;
        const unsigned long long* sbv = (const unsigned long long*)(sb + og * 16);
        int idx_base = fbid * 256;
        int b     = idx_base >> 12;
        int mbase = idx_base & 4095;
        const float* fb = feat + ((size_t)b * 64) * 4096;

#pragma unroll
        for (int it = 0; it < 2; it++) {
            int mloc = it * 128 + lane * 4;
            unsigned long long acc[4][8];
#pragma unroll
            for (int mi = 0; mi < 4; mi++)
#pragma unroll
                for (int k = 0; k < 8; k++) acc[mi][k] = sbv[k];

            const float* fp = fb + mbase + mloc;
#pragma unroll 8
            for (int c = 0; c < 64; c++) {
                float4 f4 = *(const float4*)(fp + c * 4096);
                const unsigned long long* wv =
                    (const unsigned long long*)(sw + (c * 8 + og) * 16);
                unsigned long long x0 = packdup(f4.x), x1 = packdup(f4.y);
                unsigned long long x2 = packdup(f4.z), x3 = packdup(f4.w);
#pragma unroll
                for (int k = 0; k < 8; k++) {
                    unsigned long long w = wv[k];
                    fma2(acc[0][k], w, x0);
                    fma2(acc[1][k], w, x1);
                    fma2(acc[2][k], w, x2);
                    fma2(acc[3][k], w, x3);
                }
            }
#pragma unroll
            for (int mi = 0; mi < 4; mi++) {
                float4* dst = (float4*)(g_F + ((size_t)(idx_base + mloc + mi)) * 128 + og * 16);
#pragma unroll
                for (int k = 0; k < 4; k++) {
                    float a0, a1, a2, a3;
                    unpack2(acc[mi][2 * k], a0, a1);
                    unpack2(acc[mi][2 * k + 1], a2, a3);
                    dst[k] = make_float4(a0, a1, a2, a3);
                }
            }
        }
        return;
    }

    // ================= distance path =================
    float4* sh  = (float4*)smem_raw;
    int*    buf = (int*)(sh + 4100);
    float*  red = (float*)(buf + 64 * 4 * 32);

    bool row = blockIdx.x < 128;
    int  ib  = row ? blockIdx.x : blockIdx.x - 128;
    int  pp  = t >> 2;
    int  q   = t & 3;
    int  i   = ib * 64 + pp;
    int  b   = i >> 12;
    int  x   = i & 4095;

    const float* scan = row ? knnpoints : points;
    for (int m = t; m < 4096; m += 256) {
        float qx = scan[(b * 3 + 0) * 4096 + m];
        float qy = scan[(b * 3 + 1) * 4096 + m];
        float qz = scan[(b * 3 + 2) * 4096 + m];
        sh[m + (m >> 10)] = make_float4(qx, qy, qz, fmaf(qx, qx, fmaf(qy, qy, qz * qz)));
    }
    __syncthreads();

    const float* own = row ? points : knnpoints;
    float px = own[(b * 3 + 0) * 4096 + x];
    float py = own[(b * 3 + 1) * 4096 + x];
    float pz = own[(b * 3 + 2) * 4096 + x];
    float pe = fmaf(px, px, fmaf(py, py, pz * pz));

    float minv = 3.402823e38f;
    int   c    = 0;
    int*  mybuf = buf + (pp * 4 + q) * 32;

    int mlo = q * 1024, mhi = mlo + 1024;
    for (int m0 = mlo; m0 < mhi; m0 += 4) {
        float d2v[4];
#pragma unroll
        for (int u = 0; u < 4; u++) {
            float4 qq = sh[m0 + u + q];
            float dot = fmaf(px, qq.x, fmaf(py, qq.y, pz * qq.z));
            d2v[u] = fmaxf(fmaf(-2.0f, dot, pe + qq.w), 0.0f);
        }
        minv = fminf(minv, fminf(fminf(d2v[0], d2v[1]), fminf(d2v[2], d2v[3])));
        if (row) {
            bool p0 = d2v[0] < R2, p1 = d2v[1] < R2, p2 = d2v[2] < R2, p3 = d2v[3] < R2;
            if (p0 | p1 | p2 | p3) {
                if (p0 && c < KK) { mybuf[c] = m0 + 0; c++; }
                if (p1 && c < KK) { mybuf[c] = m0 + 1; c++; }
                if (p2 && c < KK) { mybuf[c] = m0 + 2; c++; }
                if (p3 && c < KK) { mybuf[c] = m0 + 3; c++; }
            }
        }
    }

    minv = fminf(minv, __shfl_xor_sync(0xffffffffu, minv, 1));
    minv = fminf(minv, __shfl_xor_sync(0xffffffffu, minv, 2));

    if (row) {
        int lane = t & 31, g0 = lane & ~3;
        int c0 = __shfl_sync(0xffffffffu, c, g0 + 0);
        int c1 = __shfl_sync(0xffffffffu, c, g0 + 1);
        int c2 = __shfl_sync(0xffffffffu, c, g0 + 2);
        int c3 = __shfl_sync(0xffffffffu, c, g0 + 3);
        int pre = (q > 0 ? c0 : 0) + (q > 1 ? c1 : 0) + (q > 2 ? c2 : 0);
        int tot = c0 + c1 + c2 + c3;
        int base = i * KK;
        for (int ii = 0; ii < c; ii++) {
            int pos = pre + ii;
            if (pos < KK) g_idx[base + pos] = mybuf[ii];
        }
        if (q == 0) {
            int cnt = tot < KK ? tot : KK;
            g_cnt[i] = cnt;
            if (cnt == 0) g_idx[base] = 0;
        }
    }
    if (q == 0) red[pp] = sqrtf(1e-6f + minv);
    __syncthreads();
    if (t < 32) {
        float s = red[t] + red[t + 32];
#pragma unroll
        for (int off = 16; off > 0; off >>= 1) s += __shfl_xor_sync(0xffffffffu, s, off);
        if (t == 0) {
            if (row) g_rowpart[ib] = s;
            else     g_colpart[ib] = s;
        }
    }
}

// ---------------- dense column-stream MLP ----------------
// Warp region (1600 floats):
//   [0,8)   smm: m index per slot (int)
//   [8,16)  smi: point index per slot (int)
//   [16,24) smw: column weight per slot
//   [24,32) smnp: new-point flag per slot (int)
//   [32,64) diff channels [4][8]
//   [64,1088)  h1: 4 jp rows x 256 floats (XOR-swizzled 16B units)
//   [1088,1600) h2: 4 jp rows x 128 floats
#define OFF_W2 0
#define OFF_W3 8192
#define OFF_B2 12288
#define OFF_B3 12352
#define OFF_WARP 12416
#define OFF_H1 64
#define OFF_H2 1088
#define WARP_STRIDE 1600
#define SMEM_FLOATS (OFF_WARP + 16 * WARP_STRIDE)

__global__ void __launch_bounds__(512, 1) mlp_kernel(
    const float* __restrict__ points, const float* __restrict__ knnpoints,
    const float* __restrict__ w1,
    const float* __restrict__ w2, const float* __restrict__ b2,
    const float* __restrict__ w3, const float* __restrict__ b3,
    float* __restrict__ out)
{
    extern __shared__ __align__(16) unsigned char smem_raw2[];
    float* sm = (float*)smem_raw2;
    int tid = threadIdx.x;

    for (int e = tid; e < 64 * 128; e += 512) {
        int o = e >> 7, c = e & 127;
        sm[OFF_W2 + c * 64 + o] = w2[e];
    }
    for (int e = tid; e < 64 * 64; e += 512) {
        int o = e >> 6, c = e & 63;
        sm[OFF_W3 + c * 64 + o] = w3[e];
    }
    if (tid < 64) sm[OFF_B2 + tid] = b2[tid];
    if (tid < 64) sm[OFF_B3 + tid] = b3[tid];
    __syncthreads();

    int lane = tid & 31;
    int wrp  = tid >> 5;
    float* ws  = sm + OFF_WARP + wrp * WARP_STRIDE;
    float* h1p = ws + OFF_H1;
    float* h2p = ws + OFF_H2;
    int*   smm  = (int*)ws;
    int*   smi  = (int*)(ws + 8);
    float* smw  = ws + 16;
    int*   smnp = (int*)(ws + 24);
    const float2* w2v = (const float2*)(sm + OFF_W2);
    const float2* w3v = (const float2*)(sm + OFF_W3);

    unsigned long long wd1[4][4];
#pragma unroll
    for (int oo = 0; oo < 4; oo++)
#pragma unroll
        for (int ch = 0; ch < 4; ch++)
            wd1[ch][oo] = packdup(w1[(4 * lane + oo) * 68 + 64 + ch]);

    float bb2_0 = sm[OFF_B2 + 2 * lane], bb2_1 = sm[OFF_B2 + 2 * lane + 1];
    float bb3_0 = sm[OFF_B3 + 2 * lane], bb3_1 = sm[OFF_B3 + 2 * lane + 1];

    // stream state (warp-uniform)
    int cur_i = 0, cur_cols = 0, cur_j = 0;  // cur_j >= cur_cols -> exhausted
    int open_i = -1;
    float agg0 = 0.f, agg1 = 0.f;

    for (;;) {
        // ---- fill up to 8 slots from the column stream ----
        int nslots = 0;
        while (nslots < 8) {
            if (cur_j >= cur_cols) {
                int ni = 0;
                if (lane == 0) ni = (int)atomicAdd(&g_counter, 1u);
                ni = __shfl_sync(0xffffffffu, ni, 0);
                if (ni >= Bsz * Npts) { cur_cols = 0; cur_j = 0; break; }
                cur_i = ni;
                int cc = g_cnt[ni];
                cur_cols = cc > 0 ? cc : 1;
                cur_j = 0;
            }
            int take = cur_cols - cur_j;
            if (take > 8 - nslots) take = 8 - nslots;
            if (lane < take) {
                int slot = nslots + lane;
                int j = cur_j + lane;
                int m = g_idx[cur_i * KK + j];
                int b = cur_i >> 12, n = cur_i & 4095;
                smm[slot] = m;
                smi[slot] = cur_i;
                smw[slot] = (j == 0) ? (float)(KK - cur_cols + 1) : 1.0f;
                smnp[slot] = (j == 0) ? 1 : 0;
                float ppx = points[(b * 3 + 0) * 4096 + n];
                float ppy = points[(b * 3 + 1) * 4096 + n];
                float ppz = points[(b * 3 + 2) * 4096 + n];
                float qx = knnpoints[(b * 3 + 0) * 4096 + m];
                float qy = knnpoints[(b * 3 + 1) * 4096 + m];
                float qz = knnpoints[(b * 3 + 2) * 4096 + m];
                float dx = qx - ppx, dy = qy - ppy, dz = qz - ppz;
                float dd = fmaf(dx, dx, fmaf(dy, dy, dz * dz));
                ws[32 + 0 * 8 + slot] = dx;
                ws[32 + 1 * 8 + slot] = dy;
                ws[32 + 2 * 8 + slot] = dz;
                ws[32 + 3 * 8 + slot] = dd;
            }
            nslots += take;
            cur_j += take;
        }
        __syncwarp();
        if (nslots == 0) break;
        if (nslots < 8) {
            // pad with zero-weight copies of the last real slot (finite operands)
            if (lane >= nslots && lane < 8) {
                int src = nslots - 1;
                smm[lane] = smm[src];
                smi[lane] = smi[src];
                smw[lane] = 0.0f;
                smnp[lane] = 0;
                ws[32 + 0 * 8 + lane] = ws[32 + 0 * 8 + src];
                ws[32 + 1 * 8 + lane] = ws[32 + 1 * 8 + src];
                ws[32 + 2 * 8 + lane] = ws[32 + 2 * 8 + src];
                ws[32 + 3 * 8 + lane] = ws[32 + 3 * 8 + src];
            }
            __syncwarp();
        }

        // ---- layer 1: F[m] + W1d·diff (4 channels), o = 4lane..+3 ----
        {
            float4 Fv[8];
#pragma unroll
            for (int j = 0; j < 8; j++) {
                int m = smm[j];
                int pi = smi[j];
                int b = pi >> 12;
                Fv[j] = *(const float4*)(g_F + ((size_t)((b << 12) + m)) * 128 + 4 * lane);
            }
            unsigned long long xch[4][4];
#pragma unroll
            for (int ch = 0; ch < 4; ch++)
#pragma unroll
                for (int jp = 0; jp < 4; jp++)
                    xch[ch][jp] = *(const unsigned long long*)(ws + 32 + ch * 8 + 2 * jp);

            unsigned long long acc[4][4];
#pragma unroll
            for (int jp = 0; jp < 4; jp++) {
                acc[jp][0] = pack2(Fv[2 * jp].x, Fv[2 * jp + 1].x);
                acc[jp][1] = pack2(Fv[2 * jp].y, Fv[2 * jp + 1].y);
                acc[jp][2] = pack2(Fv[2 * jp].z, Fv[2 * jp + 1].z);
                acc[jp][3] = pack2(Fv[2 * jp].w, Fv[2 * jp + 1].w);
            }
#pragma unroll
            for (int ch = 0; ch < 4; ch++)
#pragma unroll
                for (int jp = 0; jp < 4; jp++)
#pragma unroll
                    for (int oo = 0; oo < 4; oo++)
                        fma2(acc[jp][oo], wd1[ch][oo], xch[ch][jp]);

            int u0 = 2 * lane, u1 = 2 * lane + 1;
            int p0 = u0 ^ ((u0 >> 3) & 7);
            int p1 = u1 ^ ((u1 >> 3) & 7);
#pragma unroll
            for (int jp = 0; jp < 4; jp++) {
                float v0, v1, v2, v3;
                unpack2(acc[jp][0], v0, v1);
                unpack2(acc[jp][1], v2, v3);
                *(float4*)(h1p + jp * 256 + p0 * 4) =
                    make_float4(fmaxf(v0, 0.f), fmaxf(v1, 0.f), fmaxf(v2, 0.f), fmaxf(v3, 0.f));
                unpack2(acc[jp][2], v0, v1);
                unpack2(acc[jp][3], v2, v3);
                *(float4*)(h1p + jp * 256 + p1 * 4) =
                    make_float4(fmaxf(v0, 0.f), fmaxf(v1, 0.f), fmaxf(v2, 0.f), fmaxf(v3, 0.f));
            }
        }
        __syncwarp();
        // ---- layer 2: 128 -> 64, lane owns o = 2lane, 2lane+1 ----
        {
            unsigned long long acc[4][2];
#pragma unroll
            for (int jp = 0; jp < 4; jp++) {
                acc[jp][0] = packdup(bb2_0);
                acc[jp][1] = packdup(bb2_1);
            }
#pragma unroll
            for (int c4 = 0; c4 < 32; c4++) {
                unsigned long long wd[4][2];
#pragma unroll
                for (int cc = 0; cc < 4; cc++) {
                    float2 w = w2v[(4 * c4 + cc) * 32 + lane];
                    wd[cc][0] = packdup(w.x); wd[cc][1] = packdup(w.y);
                }
                int ua = 2 * c4, ub = 2 * c4 + 1;
                int pa = ua ^ ((ua >> 3) & 7);
                int pb = ub ^ ((ub >> 3) & 7);
#pragma unroll
                for (int jp = 0; jp < 4; jp++) {
                    ulonglong2 XA = *(const ulonglong2*)(h1p + jp * 256 + pa * 4);
                    ulonglong2 XB = *(const ulonglong2*)(h1p + jp * 256 + pb * 4);
                    fma2(acc[jp][0], wd[0][0], XA.x); fma2(acc[jp][1], wd[0][1], XA.x);
                    fma2(acc[jp][0], wd[1][0], XA.y); fma2(acc[jp][1], wd[1][1], XA.y);
                    fma2(acc[jp][0], wd[2][0], XB.x); fma2(acc[jp][1], wd[2][1], XB.x);
                    fma2(acc[jp][0], wd[3][0], XB.y); fma2(acc[jp][1], wd[3][1], XB.y);
                }
            }
#pragma unroll
            for (int jp = 0; jp < 4; jp++) {
                float v0, v1, v2, v3;
                unpack2(acc[jp][0], v0, v1);
                unpack2(acc[jp][1], v2, v3);
                *(float4*)(h2p + jp * 128 + 4 * lane) =
                    make_float4(fmaxf(v0, 0.f), fmaxf(v1, 0.f), fmaxf(v2, 0.f), fmaxf(v3, 0.f));
            }
        }
        __syncwarp();
        // ---- layer 3: 64 -> 64 + streaming aggregate with point flush ----
        {
            unsigned long long acc[4][2];
#pragma unroll
            for (int jp = 0; jp < 4; jp++) {
                acc[jp][0] = packdup(bb3_0);
                acc[jp][1] = packdup(bb3_1);
            }
#pragma unroll
            for (int c4 = 0; c4 < 16; c4++) {
                unsigned long long wd[4][2];
#pragma unroll
                for (int cc = 0; cc < 4; cc++) {
                    float2 w = w3v[(4 * c4 + cc) * 32 + lane];
                    wd[cc][0] = packdup(w.x); wd[cc][1] = packdup(w.y);
                }
#pragma unroll
                for (int jp = 0; jp < 4; jp++) {
                    ulonglong2 XA = *(const ulonglong2*)(h2p + jp * 128 + 8 * c4);
                    ulonglong2 XB = *(const ulonglong2*)(h2p + jp * 128 + 8 * c4 + 4);
                    fma2(acc[jp][0], wd[0][0], XA.x); fma2(acc[jp][1], wd[0][1], XA.x);
                    fma2(acc[jp][0], wd[1][0], XA.y); fma2(acc[jp][1], wd[1][1], XA.y);
                    fma2(acc[jp][0], wd[2][0], XB.x); fma2(acc[jp][1], wd[2][1], XB.x);
                    fma2(acc[jp][0], wd[3][0], XB.y); fma2(acc[jp][1], wd[3][1], XB.y);
                }
            }
#pragma unroll
            for (int jp = 0; jp < 4; jp++) {
                float v00, v01, v10, v11;
                unpack2(acc[jp][0], v00, v01);
                unpack2(acc[jp][1], v10, v11);
#pragma unroll
                for (int h = 0; h < 2; h++) {
                    int col = 2 * jp + h;
                    float va = h ? v01 : v00;
                    float vb = h ? v11 : v10;
                    if (smnp[col]) {
                        if (open_i >= 0) {
                            int fb = open_i >> 12, fn = open_i & 4095;
                            out[((size_t)(fb * 64 + 2 * lane + 0)) * 4096 + fn] = agg0;
                            out[((size_t)(fb * 64 + 2 * lane + 1)) * 4096 + fn] = agg1;
                        }
                        open_i = smi[col];
                        agg0 = 0.f; agg1 = 0.f;
                    }
                    float w = smw[col];
                    agg0 = fmaf(w, fmaxf(va, 0.f), agg0);
                    agg1 = fmaf(w, fmaxf(vb, 0.f), agg1);
                }
            }
        }
        __syncwarp();
    }

    // flush the last open point
    if (open_i >= 0) {
        int fb = open_i >> 12, fn = open_i & 4095;
        out[((size_t)(fb * 64 + 2 * lane + 0)) * 4096 + fn] = agg0;
        out[((size_t)(fb * 64 + 2 * lane + 1)) * 4096 + fn] = agg1;
    }

    // ---- folded loss reduction (depends only on dist results) ----
    if (blockIdx.x == 0 && tid < 32) {
        float s = 0.f;
        for (int t = tid; t < 128; t += 32) s += g_rowpart[t] + g_colpart[t];
#pragma unroll
        for (int off = 16; off > 0; off >>= 1) s += __shfl_xor_sync(0xffffffffu, s, off);
        if (tid == 0) out[Bsz * 64 * Npts] = s * (1.0f / 8192.0f);
    }
}

extern "C" void kernel_launch(void* const* d_in, const int* in_sizes, int n_in,
                              void* d_out, int out_size) {
    const float* points    = (const float*)d_in[0];
    const float* knnpoints = (const float*)d_in[1];
    const float* feat      = (const float*)d_in[2];
    const float* w1 = (const float*)d_in[3];
    const float* b1 = (const float*)d_in[4];
    const float* w2 = (const float*)d_in[5];
    const float* b2 = (const float*)d_in[6];
    const float* w3 = (const float*)d_in[7];
    const float* b3 = (const float*)d_in[8];
    float* out = (float*)d_out;

    cudaFuncSetAttribute(distf_kernel, cudaFuncAttributeMaxDynamicSharedMemorySize, DIST_SMEM);
    cudaFuncSetAttribute(mlp_kernel,   cudaFuncAttributeMaxDynamicSharedMemorySize, SMEM_FLOATS * 4);

    int nsm = 148;
    cudaDeviceGetAttribute(&nsm, cudaDevAttrMultiProcessorCount, 0);

    distf_kernel<<<288, 256, DIST_SMEM>>>(points, knnpoints, feat, w1, b1);
    mlp_kernel<<<nsm, 512, SMEM_FLOATS * 4>>>(points, knnpoints, w1, w2, b2, w3, b3, out);
}